// round 2
// baseline (speedup 1.0000x reference)
#include <cuda_runtime.h>
#include <cuda_fp16.h>

// ---------------- problem constants ----------------
#define L_SEQ 512
#define B_N   256
#define E_DIM 128
#define H_DIM 128
#define G4    512     // 4*H
#define T_TAG 48

// ---------------- scratch (device globals; no allocation allowed) ----------------
__device__ float g_xproj_f[(size_t)L_SEQ * B_N * G4];   // 256 MiB
__device__ float g_xproj_b[(size_t)L_SEQ * B_N * G4];   // 256 MiB
__device__ float g_hf[(size_t)L_SEQ * B_N * H_DIM];     // 64 MiB
__device__ float g_hb[(size_t)L_SEQ * B_N * H_DIM];     // 64 MiB
__device__ float g_emis[(size_t)L_SEQ * B_N * T_TAG];   // 24 MiB
__device__ float g_llh[B_N];

// ---------------- helpers ----------------
__device__ __forceinline__ unsigned long long pack2(float x, float y) {
    unsigned long long r;
    asm("mov.b64 %0, {%1, %2};" : "=l"(r) : "f"(x), "f"(y));
    return r;
}
__device__ __forceinline__ void ffma2(unsigned long long& d, unsigned long long a,
                                      unsigned long long b) {
    asm("fma.rn.f32x2 %0, %1, %2, %0;" : "+l"(d) : "l"(a), "l"(b));
}
__device__ __forceinline__ float2 unpack2(unsigned long long v) {
    float2 r;
    asm("mov.b64 {%0, %1}, %2;" : "=f"(r.x), "=f"(r.y) : "l"(v));
    return r;
}
__device__ __forceinline__ float tanh_fast(float x) {
    float y;
    asm("tanh.approx.f32 %0, %1;" : "=f"(y) : "f"(x));
    return y;
}
__device__ __forceinline__ float sig_fast(float x) {
    return fmaf(0.5f, tanh_fast(0.5f * x), 0.5f);
}

// ============================================================================
// Kernel 1: xproj[l,b,g] = emb[words[b,l]] @ Wih^T + (bih + bhh)   (both dirs)
// Tile: 64 rows x 128 cols, K = 128 full. f32x2 packed FMAs.
// ============================================================================
#define XPROJ_SMEM ((64 * 128 + 128 * 130) * 4)

__global__ __launch_bounds__(256, 2) void xproj_kernel(
    const int* __restrict__ words, const float* __restrict__ emb,
    const float* __restrict__ Wih_f, const float* __restrict__ bih_f,
    const float* __restrict__ bhh_f, const float* __restrict__ Wih_b,
    const float* __restrict__ bih_b, const float* __restrict__ bhh_b) {
    extern __shared__ float sm[];
    float* A_s = sm;                 // [64][128]
    float* B_s = sm + 64 * 128;      // [128][130] : B_s[k][c] = Wih[n0+c][k]

    const int dir = blockIdx.z;
    const float* Wih = dir ? Wih_b : Wih_f;
    const float* b1  = dir ? bih_b : bih_f;
    const float* b2  = dir ? bhh_b : bhh_f;
    float* out       = dir ? g_xproj_b : g_xproj_f;

    const int row0 = blockIdx.y * 64;
    const int n0   = blockIdx.x * 128;
    const int tid  = threadIdx.x;

    // Load A tile: gather embedding rows (row = l*B + b)
    for (int i = tid; i < 64 * 32; i += 256) {
        int r = i >> 5;
        int k4 = i & 31;
        int grow = row0 + r;
        int l = grow >> 8;
        int b = grow & 255;
        int w = words[b * L_SEQ + l];
        float4 v = *(const float4*)(emb + (size_t)w * E_DIM + k4 * 4);
        *(float4*)(&A_s[r * 128 + k4 * 4]) = v;
    }
    // Load B tile transposed: coalesced global (lanes over k), 2-way STS conflict
    for (int i = tid; i < 128 * 128; i += 256) {
        int k = i & 127;
        int c = i >> 7;
        B_s[k * 130 + c] = Wih[(size_t)(n0 + c) * E_DIM + k];
    }
    __syncthreads();

    const int ti = tid >> 4;   // 0..15 -> 4 rows each
    const int tj = tid & 15;   // 0..15 -> 8 cols each
    unsigned long long acc[4][4];
#pragma unroll
    for (int r = 0; r < 4; r++)
#pragma unroll
        for (int u = 0; u < 4; u++) acc[r][u] = 0ull;

#pragma unroll 8
    for (int k = 0; k < 128; ++k) {
        const float* brow = B_s + k * 130 + tj * 8;
        unsigned long long bv0 = *(const unsigned long long*)(brow + 0);
        unsigned long long bv1 = *(const unsigned long long*)(brow + 2);
        unsigned long long bv2 = *(const unsigned long long*)(brow + 4);
        unsigned long long bv3 = *(const unsigned long long*)(brow + 6);
#pragma unroll
        for (int rr = 0; rr < 4; rr++) {
            float a = A_s[(ti * 4 + rr) * 128 + k];
            unsigned long long a2 = pack2(a, a);
            ffma2(acc[rr][0], a2, bv0);
            ffma2(acc[rr][1], a2, bv1);
            ffma2(acc[rr][2], a2, bv2);
            ffma2(acc[rr][3], a2, bv3);
        }
    }

    // epilogue: bias (bih+bhh) and store
    float bx[4], by[4];
#pragma unroll
    for (int u = 0; u < 4; u++) {
        int cc = n0 + tj * 8 + u * 2;
        bx[u] = b1[cc] + b2[cc];
        by[u] = b1[cc + 1] + b2[cc + 1];
    }
#pragma unroll
    for (int rr = 0; rr < 4; rr++) {
        int gr = row0 + ti * 4 + rr;
#pragma unroll
        for (int u = 0; u < 4; u++) {
            float2 v = unpack2(acc[rr][u]);
            int cc = n0 + tj * 8 + u * 2;
            float2 o = make_float2(v.x + bx[u], v.y + by[u]);
            *(float2*)(out + (size_t)gr * G4 + cc) = o;
        }
    }
}

// ============================================================================
// Kernel 2: LSTM recurrence, both directions. One CTA = 4 batch lanes.
// Whh as fp16 in smem [k][g] with 514-half row pad (conflict-free both ways).
// h stored [k][b] so one broadcast 16B LDS feeds two f32x2 FMAs.
// ============================================================================
#define LSTM_SMEM (128 * 4 * 4 + 4 * 512 * 4 + 128 * 514 * 2)

__global__ __launch_bounds__(512, 1) void lstm_kernel(const float* __restrict__ Whh_f,
                                                      const float* __restrict__ Whh_b) {
    extern __shared__ char smraw[];
    float* h_s   = (float*)smraw;                     // [128][4]
    float* pre_s = h_s + 128 * 4;                     // [4][512]
    __half* w_s  = (__half*)(pre_s + 4 * 512);        // [128][514]

    const int tid = threadIdx.x;       // gate index g (0..511)
    const int dir = blockIdx.y;
    const int b0  = blockIdx.x * 4;
    const float* Whh = dir ? Whh_b : Whh_f;
    const float* xp  = dir ? g_xproj_b : g_xproj_f;
    float* hout      = dir ? g_hb : g_hf;

    // load Whh -> smem fp16, transposed. lanes over k: coalesced LDG + clean STS.
#pragma unroll 4
    for (int it = 0; it < 128; ++it) {
        int idx = it * 512 + tid;
        int k = idx & 127;
        int g = idx >> 7;
        w_s[k * 514 + g] = __float2half(Whh[g * 128 + k]);
    }
    if (tid < 128) {
        *(float4*)&h_s[tid * 4] = make_float4(0.f, 0.f, 0.f, 0.f);
    }
    float c[4] = {0.f, 0.f, 0.f, 0.f};
    __syncthreads();

    for (int s = 0; s < L_SEQ; ++s) {
        const int l = dir ? (L_SEQ - 1 - s) : s;
        // prefetch this step's x-projection (issued early, consumed post-GEMM)
        const float* xrow = xp + ((size_t)l * B_N + b0) * G4 + tid;
        float x0 = xrow[0];
        float x1 = xrow[512];
        float x2 = xrow[1024];
        float x3 = xrow[1536];

        unsigned long long acc01 = 0ull, acc23 = 0ull;
#pragma unroll 16
        for (int k = 0; k < 128; ++k) {
            float w = __half2float(w_s[k * 514 + tid]);
            unsigned long long w2 = pack2(w, w);
            unsigned long long h01 = *(const unsigned long long*)&h_s[k * 4];
            unsigned long long h23 = *(const unsigned long long*)&h_s[k * 4 + 2];
            ffma2(acc01, w2, h01);
            ffma2(acc23, w2, h23);
        }
        float2 a01 = unpack2(acc01);
        float2 a23 = unpack2(acc23);
        pre_s[0 * 512 + tid] = a01.x + x0;
        pre_s[1 * 512 + tid] = a01.y + x1;
        pre_s[2 * 512 + tid] = a23.x + x2;
        pre_s[3 * 512 + tid] = a23.y + x3;
        __syncthreads();

        if (tid < 128) {
            float hv[4];
#pragma unroll
            for (int bb = 0; bb < 4; ++bb) {
                float gi = pre_s[bb * 512 + tid];
                float gf = pre_s[bb * 512 + tid + 128];
                float gg = pre_s[bb * 512 + tid + 256];
                float go = pre_s[bb * 512 + tid + 384];
                float cn = sig_fast(gf) * c[bb] + sig_fast(gi) * tanh_fast(gg);
                c[bb] = cn;
                hv[bb] = sig_fast(go) * tanh_fast(cn);
            }
            *(float4*)&h_s[tid * 4] = make_float4(hv[0], hv[1], hv[2], hv[3]);
            size_t ho = ((size_t)l * B_N + b0) * H_DIM + tid;
            hout[ho]       = hv[0];
            hout[ho + 128] = hv[1];
            hout[ho + 256] = hv[2];
            hout[ho + 384] = hv[3];
        }
        __syncthreads();
    }
}

// ============================================================================
// Kernel 3: emis[l,b,t] = [h_f|h_b] . Wout[t] + bout[t]
// ============================================================================
#define EMIS_SMEM ((48 * 257 + 16 * 256) * 4)

__global__ __launch_bounds__(256) void emis_kernel(const float* __restrict__ Wout,
                                                   const float* __restrict__ bout) {
    extern __shared__ float sm[];
    float* Wout_s = sm;                  // [48][257] padded
    float* hrow   = sm + 48 * 257;       // [16][256]

    const int tid = threadIdx.x;
    const int row0 = blockIdx.x * 16;    // row = l*B + b

    for (int i = tid; i < 48 * 256; i += 256) {
        int t = i >> 8;
        int k = i & 255;
        Wout_s[t * 257 + k] = Wout[i];
    }
    for (int i = tid; i < 16 * 256; i += 256) {
        int r = i >> 8;
        int k = i & 255;
        int grow = row0 + r;
        hrow[r * 256 + k] =
            (k < 128) ? g_hf[(size_t)grow * 128 + k] : g_hb[(size_t)grow * 128 + (k - 128)];
    }
    __syncthreads();

    for (int o = tid; o < 16 * 48; o += 256) {
        int r = o / 48;
        int t = o % 48;
        float acc = bout[t];
        const float* hp = hrow + r * 256;
        const float* wp = Wout_s + t * 257;
#pragma unroll 8
        for (int k = 0; k < 256; ++k) acc = fmaf(hp[k], wp[k], acc);
        g_emis[(size_t)(row0 + r) * T_TAG + t] = acc;
    }
}

// ============================================================================
// Kernel 4: CRF numerator + forward algorithm per batch element.
// mask[b,l] == (words[b,l] != 0) (prefix mask by construction).
// ============================================================================
__global__ __launch_bounds__(64) void crf_kernel(const int* __restrict__ words,
                                                 const int* __restrict__ tags,
                                                 const float* __restrict__ trans,
                                                 const float* __restrict__ start_trans,
                                                 const float* __restrict__ end_trans) {
    __shared__ float trans_s[48 * 48];
    __shared__ float score_s[48];
    __shared__ float red[64];

    const int b = blockIdx.x;
    const int tid = threadIdx.x;

    for (int i = tid; i < 48 * 48; i += 64) trans_s[i] = trans[i];

    // sequence length (prefix mask -> count of nonzero words)
    int cnt = 0;
    for (int l = tid; l < L_SEQ; l += 64) cnt += (words[b * L_SEQ + l] != 0) ? 1 : 0;
    red[tid] = (float)cnt;
    __syncthreads();
    for (int sft = 32; sft > 0; sft >>= 1) {
        if (tid < sft) red[tid] += red[tid + sft];
        __syncthreads();
    }
    const int len = (int)red[0];
    __syncthreads();

    // numerator partials (l = 1 .. len-1)
    float np = 0.f;
    for (int l = 1 + tid; l < len; l += 64) {
        int tp = tags[b * L_SEQ + l - 1];
        int tc = tags[b * L_SEQ + l];
        np += trans_s[tp * 48 + tc] + g_emis[((size_t)l * B_N + b) * T_TAG + tc];
    }
    red[tid] = np;
    __syncthreads();
    for (int sft = 32; sft > 0; sft >>= 1) {
        if (tid < sft) red[tid] += red[tid + sft];
        __syncthreads();
    }
    // red[0] now holds the interior numerator sum; keep it intact below.

    // denominator: forward algorithm
    if (tid < 48) score_s[tid] = start_trans[tid] + g_emis[(size_t)b * T_TAG + tid];
    __syncthreads();
    for (int l = 1; l < len; ++l) {
        float nv = 0.f;
        if (tid < 48) {
            float em = g_emis[((size_t)l * B_N + b) * T_TAG + tid];
            float mx = -1e30f;
#pragma unroll 8
            for (int i = 0; i < 48; ++i) mx = fmaxf(mx, score_s[i] + trans_s[i * 48 + tid]);
            float ssum = 0.f;
#pragma unroll 8
            for (int i = 0; i < 48; ++i)
                ssum += __expf(score_s[i] + trans_s[i * 48 + tid] - mx);
            nv = mx + __logf(ssum) + em;
        }
        __syncthreads();
        if (tid < 48) score_s[tid] = nv;
        __syncthreads();
    }

    if (tid == 0) {
        float mx = -1e30f;
        for (int j = 0; j < 48; ++j) mx = fmaxf(mx, score_s[j] + end_trans[j]);
        float ssum = 0.f;
        for (int j = 0; j < 48; ++j) ssum += __expf(score_s[j] + end_trans[j] - mx);
        float denom = mx + __logf(ssum);

        int t0 = tags[b * L_SEQ + 0];
        int tlast = tags[b * L_SEQ + (len - 1)];
        float num = red[0] + start_trans[t0] + g_emis[(size_t)b * T_TAG + t0] + end_trans[tlast];
        g_llh[b] = num - denom;
    }
}

// ============================================================================
// Kernel 5: final reduction -> out[0] = -mean(llh)
// ============================================================================
__global__ __launch_bounds__(256) void final_kernel(float* __restrict__ out) {
    __shared__ float red[256];
    int tid = threadIdx.x;
    red[tid] = g_llh[tid];
    __syncthreads();
    for (int s = 128; s > 0; s >>= 1) {
        if (tid < s) red[tid] += red[tid + s];
        __syncthreads();
    }
    if (tid == 0) out[0] = -red[0] / (float)B_N;
}

// ============================================================================
// launch
// ============================================================================
extern "C" void kernel_launch(void* const* d_in, const int* in_sizes, int n_in,
                              void* d_out, int out_size) {
    const int*   words  = (const int*)d_in[0];
    const int*   tags   = (const int*)d_in[1];
    // d_in[2] = mask (unused; derived from words != 0)
    const float* emb    = (const float*)d_in[3];
    const float* Wih_f  = (const float*)d_in[4];
    const float* Whh_f  = (const float*)d_in[5];
    const float* bih_f  = (const float*)d_in[6];
    const float* bhh_f  = (const float*)d_in[7];
    const float* Wih_b  = (const float*)d_in[8];
    const float* Whh_b  = (const float*)d_in[9];
    const float* bih_b  = (const float*)d_in[10];
    const float* bhh_b  = (const float*)d_in[11];
    const float* Wout   = (const float*)d_in[12];
    const float* bout   = (const float*)d_in[13];
    const float* trans  = (const float*)d_in[14];
    const float* st     = (const float*)d_in[15];
    const float* et     = (const float*)d_in[16];
    float* out = (float*)d_out;

    cudaFuncSetAttribute(xproj_kernel, cudaFuncAttributeMaxDynamicSharedMemorySize,
                         XPROJ_SMEM);
    cudaFuncSetAttribute(lstm_kernel, cudaFuncAttributeMaxDynamicSharedMemorySize,
                         LSTM_SMEM);
    cudaFuncSetAttribute(emis_kernel, cudaFuncAttributeMaxDynamicSharedMemorySize,
                         EMIS_SMEM);

    // 1) input projections for both directions (embedding gather fused)
    xproj_kernel<<<dim3(4, (L_SEQ * B_N) / 64, 2), 256, XPROJ_SMEM>>>(
        words, emb, Wih_f, bih_f, bhh_f, Wih_b, bih_b, bhh_b);

    // 2) recurrent BiLSTM: 64 CTAs x 2 directions, 4 batch lanes per CTA
    lstm_kernel<<<dim3(B_N / 4, 2), 512, LSTM_SMEM>>>(Whh_f, Whh_b);

    // 3) emissions
    emis_kernel<<<(L_SEQ * B_N) / 16, 256, EMIS_SMEM>>>(Wout, bout);

    // 4) CRF per batch element
    crf_kernel<<<B_N, 64>>>(words, tags, trans, st, et);

    // 5) reduce to scalar
    final_kernel<<<1, 256>>>(out);
}

// round 3
// speedup vs baseline: 1.0001x; 1.0001x over previous
#include <cuda_runtime.h>
#include <cuda_fp16.h>

// ---------------- problem constants ----------------
#define L_SEQ 512
#define B_N   256
#define E_DIM 128
#define H_DIM 128
#define G4    512     // 4*H
#define T_TAG 48

// ---------------- scratch (device globals; no allocation allowed) ----------------
__device__ float g_xproj_f[(size_t)L_SEQ * B_N * G4];   // 256 MiB
__device__ float g_xproj_b[(size_t)L_SEQ * B_N * G4];   // 256 MiB
__device__ float g_hf[(size_t)L_SEQ * B_N * H_DIM];     // 64 MiB
__device__ float g_hb[(size_t)L_SEQ * B_N * H_DIM];     // 64 MiB
__device__ float g_emis[(size_t)L_SEQ * B_N * T_TAG];   // 24 MiB
__device__ float g_llh[B_N];

// ---------------- helpers ----------------
__device__ __forceinline__ unsigned long long pack2(float x, float y) {
    unsigned long long r;
    asm("mov.b64 %0, {%1, %2};" : "=l"(r) : "f"(x), "f"(y));
    return r;
}
__device__ __forceinline__ void ffma2(unsigned long long& d, unsigned long long a,
                                      unsigned long long b) {
    asm("fma.rn.f32x2 %0, %1, %2, %0;" : "+l"(d) : "l"(a), "l"(b));
}
__device__ __forceinline__ float2 unpack2(unsigned long long v) {
    float2 r;
    asm("mov.b64 {%0, %1}, %2;" : "=f"(r.x), "=f"(r.y) : "l"(v));
    return r;
}
__device__ __forceinline__ float tanh_fast(float x) {
    float y;
    asm("tanh.approx.f32 %0, %1;" : "=f"(y) : "f"(x));
    return y;
}
__device__ __forceinline__ float sig_fast(float x) {
    return fmaf(0.5f, tanh_fast(0.5f * x), 0.5f);
}

// ============================================================================
// Kernel 1: xproj[l,b,g] = emb[words[b,l]] @ Wih^T + (bih + bhh)   (both dirs)
// Tile: 64 rows x 128 cols, K = 128 full. f32x2 packed FMAs.
// ============================================================================
#define XPROJ_SMEM ((64 * 128 + 128 * 130) * 4)

__global__ __launch_bounds__(256, 2) void xproj_kernel(
    const int* __restrict__ words, const float* __restrict__ emb,
    const float* __restrict__ Wih_f, const float* __restrict__ bih_f,
    const float* __restrict__ bhh_f, const float* __restrict__ Wih_b,
    const float* __restrict__ bih_b, const float* __restrict__ bhh_b) {
    extern __shared__ float sm[];
    float* A_s = sm;                 // [64][128]
    float* B_s = sm + 64 * 128;      // [128][130] : B_s[k][c] = Wih[n0+c][k]

    const int dir = blockIdx.z;
    const float* Wih = dir ? Wih_b : Wih_f;
    const float* b1  = dir ? bih_b : bih_f;
    const float* b2  = dir ? bhh_b : bhh_f;
    float* out       = dir ? g_xproj_b : g_xproj_f;

    const int row0 = blockIdx.y * 64;
    const int n0   = blockIdx.x * 128;
    const int tid  = threadIdx.x;

    // Load A tile: gather embedding rows (row = l*B + b)
    for (int i = tid; i < 64 * 32; i += 256) {
        int r = i >> 5;
        int k4 = i & 31;
        int grow = row0 + r;
        int l = grow >> 8;
        int b = grow & 255;
        int w = words[b * L_SEQ + l];
        float4 v = *(const float4*)(emb + (size_t)w * E_DIM + k4 * 4);
        *(float4*)(&A_s[r * 128 + k4 * 4]) = v;
    }
    // Load B tile transposed: coalesced global (lanes over k), 2-way STS conflict
    for (int i = tid; i < 128 * 128; i += 256) {
        int k = i & 127;
        int c = i >> 7;
        B_s[k * 130 + c] = Wih[(size_t)(n0 + c) * E_DIM + k];
    }
    __syncthreads();

    const int ti = tid >> 4;   // 0..15 -> 4 rows each
    const int tj = tid & 15;   // 0..15 -> 8 cols each
    unsigned long long acc[4][4];
#pragma unroll
    for (int r = 0; r < 4; r++)
#pragma unroll
        for (int u = 0; u < 4; u++) acc[r][u] = 0ull;

#pragma unroll 8
    for (int k = 0; k < 128; ++k) {
        const float* brow = B_s + k * 130 + tj * 8;
        unsigned long long bv0 = *(const unsigned long long*)(brow + 0);
        unsigned long long bv1 = *(const unsigned long long*)(brow + 2);
        unsigned long long bv2 = *(const unsigned long long*)(brow + 4);
        unsigned long long bv3 = *(const unsigned long long*)(brow + 6);
#pragma unroll
        for (int rr = 0; rr < 4; rr++) {
            float a = A_s[(ti * 4 + rr) * 128 + k];
            unsigned long long a2 = pack2(a, a);
            ffma2(acc[rr][0], a2, bv0);
            ffma2(acc[rr][1], a2, bv1);
            ffma2(acc[rr][2], a2, bv2);
            ffma2(acc[rr][3], a2, bv3);
        }
    }

    // epilogue: bias (bih+bhh) and store
    float bx[4], by[4];
#pragma unroll
    for (int u = 0; u < 4; u++) {
        int cc = n0 + tj * 8 + u * 2;
        bx[u] = b1[cc] + b2[cc];
        by[u] = b1[cc + 1] + b2[cc + 1];
    }
#pragma unroll
    for (int rr = 0; rr < 4; rr++) {
        int gr = row0 + ti * 4 + rr;
#pragma unroll
        for (int u = 0; u < 4; u++) {
            float2 v = unpack2(acc[rr][u]);
            int cc = n0 + tj * 8 + u * 2;
            float2 o = make_float2(v.x + bx[u], v.y + by[u]);
            *(float2*)(out + (size_t)gr * G4 + cc) = o;
        }
    }
}

// ============================================================================
// Kernel 2: LSTM recurrence, both directions. One CTA = 4 batch lanes.
// Whh as fp16 in smem [k][g] with 514-half row pad (conflict-free both ways).
// h stored [k][b] so one broadcast 16B LDS feeds two f32x2 FMAs.
// ============================================================================
#define LSTM_SMEM (128 * 4 * 4 + 4 * 512 * 4 + 128 * 514 * 2)

__global__ __launch_bounds__(512, 1) void lstm_kernel(const float* __restrict__ Whh_f,
                                                      const float* __restrict__ Whh_b) {
    extern __shared__ char smraw[];
    float* h_s   = (float*)smraw;                     // [128][4]
    float* pre_s = h_s + 128 * 4;                     // [4][512]
    __half* w_s  = (__half*)(pre_s + 4 * 512);        // [128][514]

    const int tid = threadIdx.x;       // gate index g (0..511)
    const int dir = blockIdx.y;
    const int b0  = blockIdx.x * 4;
    const float* Whh = dir ? Whh_b : Whh_f;
    const float* xp  = dir ? g_xproj_b : g_xproj_f;
    float* hout      = dir ? g_hb : g_hf;

    // load Whh -> smem fp16, transposed. lanes over k: coalesced LDG + clean STS.
#pragma unroll 4
    for (int it = 0; it < 128; ++it) {
        int idx = it * 512 + tid;
        int k = idx & 127;
        int g = idx >> 7;
        w_s[k * 514 + g] = __float2half(Whh[g * 128 + k]);
    }
    if (tid < 128) {
        *(float4*)&h_s[tid * 4] = make_float4(0.f, 0.f, 0.f, 0.f);
    }
    float c[4] = {0.f, 0.f, 0.f, 0.f};
    __syncthreads();

    for (int s = 0; s < L_SEQ; ++s) {
        const int l = dir ? (L_SEQ - 1 - s) : s;
        // prefetch this step's x-projection (issued early, consumed post-GEMM)
        const float* xrow = xp + ((size_t)l * B_N + b0) * G4 + tid;
        float x0 = xrow[0];
        float x1 = xrow[512];
        float x2 = xrow[1024];
        float x3 = xrow[1536];

        unsigned long long acc01 = 0ull, acc23 = 0ull;
#pragma unroll 16
        for (int k = 0; k < 128; ++k) {
            float w = __half2float(w_s[k * 514 + tid]);
            unsigned long long w2 = pack2(w, w);
            unsigned long long h01 = *(const unsigned long long*)&h_s[k * 4];
            unsigned long long h23 = *(const unsigned long long*)&h_s[k * 4 + 2];
            ffma2(acc01, w2, h01);
            ffma2(acc23, w2, h23);
        }
        float2 a01 = unpack2(acc01);
        float2 a23 = unpack2(acc23);
        pre_s[0 * 512 + tid] = a01.x + x0;
        pre_s[1 * 512 + tid] = a01.y + x1;
        pre_s[2 * 512 + tid] = a23.x + x2;
        pre_s[3 * 512 + tid] = a23.y + x3;
        __syncthreads();

        if (tid < 128) {
            float hv[4];
#pragma unroll
            for (int bb = 0; bb < 4; ++bb) {
                float gi = pre_s[bb * 512 + tid];
                float gf = pre_s[bb * 512 + tid + 128];
                float gg = pre_s[bb * 512 + tid + 256];
                float go = pre_s[bb * 512 + tid + 384];
                float cn = sig_fast(gf) * c[bb] + sig_fast(gi) * tanh_fast(gg);
                c[bb] = cn;
                hv[bb] = sig_fast(go) * tanh_fast(cn);
            }
            *(float4*)&h_s[tid * 4] = make_float4(hv[0], hv[1], hv[2], hv[3]);
            size_t ho = ((size_t)l * B_N + b0) * H_DIM + tid;
            hout[ho]       = hv[0];
            hout[ho + 128] = hv[1];
            hout[ho + 256] = hv[2];
            hout[ho + 384] = hv[3];
        }
        __syncthreads();
    }
}

// ============================================================================
// Kernel 3: emis[l,b,t] = [h_f|h_b] . Wout[t] + bout[t]
// ============================================================================
#define EMIS_SMEM ((48 * 257 + 16 * 256) * 4)

__global__ __launch_bounds__(256) void emis_kernel(const float* __restrict__ Wout,
                                                   const float* __restrict__ bout) {
    extern __shared__ float sm[];
    float* Wout_s = sm;                  // [48][257] padded
    float* hrow   = sm + 48 * 257;       // [16][256]

    const int tid = threadIdx.x;
    const int row0 = blockIdx.x * 16;    // row = l*B + b

    for (int i = tid; i < 48 * 256; i += 256) {
        int t = i >> 8;
        int k = i & 255;
        Wout_s[t * 257 + k] = Wout[i];
    }
    for (int i = tid; i < 16 * 256; i += 256) {
        int r = i >> 8;
        int k = i & 255;
        int grow = row0 + r;
        hrow[r * 256 + k] =
            (k < 128) ? g_hf[(size_t)grow * 128 + k] : g_hb[(size_t)grow * 128 + (k - 128)];
    }
    __syncthreads();

    for (int o = tid; o < 16 * 48; o += 256) {
        int r = o / 48;
        int t = o % 48;
        float acc = bout[t];
        const float* hp = hrow + r * 256;
        const float* wp = Wout_s + t * 257;
#pragma unroll 8
        for (int k = 0; k < 256; ++k) acc = fmaf(hp[k], wp[k], acc);
        g_emis[(size_t)(row0 + r) * T_TAG + t] = acc;
    }
}

// ============================================================================
// Kernel 4: CRF numerator + forward algorithm per batch element.
// mask[b,l] == (words[b,l] != 0) (prefix mask by construction).
// ============================================================================
__global__ __launch_bounds__(64) void crf_kernel(const int* __restrict__ words,
                                                 const int* __restrict__ tags,
                                                 const float* __restrict__ trans,
                                                 const float* __restrict__ start_trans,
                                                 const float* __restrict__ end_trans) {
    __shared__ float trans_s[48 * 48];
    __shared__ float score_s[48];
    __shared__ float red[64];

    const int b = blockIdx.x;
    const int tid = threadIdx.x;

    for (int i = tid; i < 48 * 48; i += 64) trans_s[i] = trans[i];

    // sequence length (prefix mask -> count of nonzero words)
    int cnt = 0;
    for (int l = tid; l < L_SEQ; l += 64) cnt += (words[b * L_SEQ + l] != 0) ? 1 : 0;
    red[tid] = (float)cnt;
    __syncthreads();
    for (int sft = 32; sft > 0; sft >>= 1) {
        if (tid < sft) red[tid] += red[tid + sft];
        __syncthreads();
    }
    const int len = (int)red[0];
    __syncthreads();

    // numerator partials (l = 1 .. len-1)
    float np = 0.f;
    for (int l = 1 + tid; l < len; l += 64) {
        int tp = tags[b * L_SEQ + l - 1];
        int tc = tags[b * L_SEQ + l];
        np += trans_s[tp * 48 + tc] + g_emis[((size_t)l * B_N + b) * T_TAG + tc];
    }
    red[tid] = np;
    __syncthreads();
    for (int sft = 32; sft > 0; sft >>= 1) {
        if (tid < sft) red[tid] += red[tid + sft];
        __syncthreads();
    }
    // red[0] now holds the interior numerator sum; keep it intact below.

    // denominator: forward algorithm
    if (tid < 48) score_s[tid] = start_trans[tid] + g_emis[(size_t)b * T_TAG + tid];
    __syncthreads();
    for (int l = 1; l < len; ++l) {
        float nv = 0.f;
        if (tid < 48) {
            float em = g_emis[((size_t)l * B_N + b) * T_TAG + tid];
            float mx = -1e30f;
#pragma unroll 8
            for (int i = 0; i < 48; ++i) mx = fmaxf(mx, score_s[i] + trans_s[i * 48 + tid]);
            float ssum = 0.f;
#pragma unroll 8
            for (int i = 0; i < 48; ++i)
                ssum += __expf(score_s[i] + trans_s[i * 48 + tid] - mx);
            nv = mx + __logf(ssum) + em;
        }
        __syncthreads();
        if (tid < 48) score_s[tid] = nv;
        __syncthreads();
    }

    if (tid == 0) {
        float mx = -1e30f;
        for (int j = 0; j < 48; ++j) mx = fmaxf(mx, score_s[j] + end_trans[j]);
        float ssum = 0.f;
        for (int j = 0; j < 48; ++j) ssum += __expf(score_s[j] + end_trans[j] - mx);
        float denom = mx + __logf(ssum);

        int t0 = tags[b * L_SEQ + 0];
        int tlast = tags[b * L_SEQ + (len - 1)];
        float num = red[0] + start_trans[t0] + g_emis[(size_t)b * T_TAG + t0] + end_trans[tlast];
        g_llh[b] = num - denom;
    }
}

// ============================================================================
// Kernel 5: final reduction -> out[0] = -mean(llh)
// ============================================================================
__global__ __launch_bounds__(256) void final_kernel(float* __restrict__ out) {
    __shared__ float red[256];
    int tid = threadIdx.x;
    red[tid] = g_llh[tid];
    __syncthreads();
    for (int s = 128; s > 0; s >>= 1) {
        if (tid < s) red[tid] += red[tid + s];
        __syncthreads();
    }
    if (tid == 0) out[0] = -red[0] / (float)B_N;
}

// ============================================================================
// launch
// ============================================================================
extern "C" void kernel_launch(void* const* d_in, const int* in_sizes, int n_in,
                              void* d_out, int out_size) {
    const int*   words  = (const int*)d_in[0];
    const int*   tags   = (const int*)d_in[1];
    // d_in[2] = mask (unused; derived from words != 0)
    const float* emb    = (const float*)d_in[3];
    const float* Wih_f  = (const float*)d_in[4];
    const float* Whh_f  = (const float*)d_in[5];
    const float* bih_f  = (const float*)d_in[6];
    const float* bhh_f  = (const float*)d_in[7];
    const float* Wih_b  = (const float*)d_in[8];
    const float* Whh_b  = (const float*)d_in[9];
    const float* bih_b  = (const float*)d_in[10];
    const float* bhh_b  = (const float*)d_in[11];
    const float* Wout   = (const float*)d_in[12];
    const float* bout   = (const float*)d_in[13];
    const float* trans  = (const float*)d_in[14];
    const float* st     = (const float*)d_in[15];
    const float* et     = (const float*)d_in[16];
    float* out = (float*)d_out;

    cudaFuncSetAttribute(xproj_kernel, cudaFuncAttributeMaxDynamicSharedMemorySize,
                         XPROJ_SMEM);
    cudaFuncSetAttribute(lstm_kernel, cudaFuncAttributeMaxDynamicSharedMemorySize,
                         LSTM_SMEM);
    cudaFuncSetAttribute(emis_kernel, cudaFuncAttributeMaxDynamicSharedMemorySize,
                         EMIS_SMEM);

    // 1) input projections for both directions (embedding gather fused)
    xproj_kernel<<<dim3(4, (L_SEQ * B_N) / 64, 2), 256, XPROJ_SMEM>>>(
        words, emb, Wih_f, bih_f, bhh_f, Wih_b, bih_b, bhh_b);

    // 2) recurrent BiLSTM: 64 CTAs x 2 directions, 4 batch lanes per CTA
    lstm_kernel<<<dim3(B_N / 4, 2), 512, LSTM_SMEM>>>(Whh_f, Whh_b);

    // 3) emissions
    emis_kernel<<<(L_SEQ * B_N) / 16, 256, EMIS_SMEM>>>(Wout, bout);

    // 4) CRF per batch element
    crf_kernel<<<B_N, 64>>>(words, tags, trans, st, et);

    // 5) reduce to scalar
    final_kernel<<<1, 256>>>(out);
}

// round 4
// speedup vs baseline: 1.2343x; 1.2342x over previous
#include <cuda_runtime.h>
#include <cuda_fp16.h>

// ---------------- problem constants ----------------
#define L_SEQ 512
#define B_N   256
#define E_DIM 128
#define H_DIM 128
#define G4    512     // 4*H
#define T_TAG 48

typedef unsigned long long ull;

// ---------------- scratch (device globals; no allocation allowed) ----------------
__device__ float g_xproj_f[(size_t)L_SEQ * B_N * G4];   // 256 MiB
__device__ float g_xproj_b[(size_t)L_SEQ * B_N * G4];   // 256 MiB
__device__ float g_hcat[(size_t)L_SEQ * B_N * 256];     // 128 MiB  [l][b][2H]
__device__ float g_emis[(size_t)L_SEQ * B_N * T_TAG];   // 24 MiB
__device__ float g_llh[B_N];

// ---------------- helpers ----------------
__device__ __forceinline__ ull pack2(float x, float y) {
    ull r;
    asm("mov.b64 %0, {%1, %2};" : "=l"(r) : "f"(x), "f"(y));
    return r;
}
__device__ __forceinline__ void ffma2(ull& d, ull a, ull b) {
    asm("fma.rn.f32x2 %0, %1, %2, %0;" : "+l"(d) : "l"(a), "l"(b));
}
__device__ __forceinline__ float2 unpack2(ull v) {
    float2 r;
    asm("mov.b64 {%0, %1}, %2;" : "=f"(r.x), "=f"(r.y) : "l"(v));
    return r;
}
__device__ __forceinline__ float tanh_fast(float x) {
    float y;
    asm("tanh.approx.f32 %0, %1;" : "=f"(y) : "f"(x));
    return y;
}
__device__ __forceinline__ float sig_fast(float x) {
    return fmaf(0.5f, tanh_fast(0.5f * x), 0.5f);
}

// ============================================================================
// Kernel 1: xproj[l,b,g] = emb[words[b,l]] @ Wih^T + (bih + bhh)   (both dirs)
// Tile: 64 rows x 128 cols, K = 128 full. f32x2 packed FMAs.
// ============================================================================
#define XPROJ_SMEM ((64 * 128 + 128 * 130) * 4)

__global__ __launch_bounds__(256, 2) void xproj_kernel(
    const int* __restrict__ words, const float* __restrict__ emb,
    const float* __restrict__ Wih_f, const float* __restrict__ bih_f,
    const float* __restrict__ bhh_f, const float* __restrict__ Wih_b,
    const float* __restrict__ bih_b, const float* __restrict__ bhh_b) {
    extern __shared__ float sm[];
    float* A_s = sm;                 // [64][128]
    float* B_s = sm + 64 * 128;      // [128][130] : B_s[k][c] = Wih[n0+c][k]

    const int dir = blockIdx.z;
    const float* Wih = dir ? Wih_b : Wih_f;
    const float* b1  = dir ? bih_b : bih_f;
    const float* b2  = dir ? bhh_b : bhh_f;
    float* out       = dir ? g_xproj_b : g_xproj_f;

    const int row0 = blockIdx.y * 64;
    const int n0   = blockIdx.x * 128;
    const int tid  = threadIdx.x;

    for (int i = tid; i < 64 * 32; i += 256) {
        int r = i >> 5;
        int k4 = i & 31;
        int grow = row0 + r;
        int l = grow >> 8;
        int b = grow & 255;
        int w = words[b * L_SEQ + l];
        float4 v = *(const float4*)(emb + (size_t)w * E_DIM + k4 * 4);
        *(float4*)(&A_s[r * 128 + k4 * 4]) = v;
    }
    for (int i = tid; i < 128 * 128; i += 256) {
        int k = i & 127;
        int c = i >> 7;
        B_s[k * 130 + c] = Wih[(size_t)(n0 + c) * E_DIM + k];
    }
    __syncthreads();

    const int ti = tid >> 4;   // 0..15 -> 4 rows each
    const int tj = tid & 15;   // 0..15 -> 8 cols each
    ull acc[4][4];
#pragma unroll
    for (int r = 0; r < 4; r++)
#pragma unroll
        for (int u = 0; u < 4; u++) acc[r][u] = 0ull;

#pragma unroll 8
    for (int k = 0; k < 128; ++k) {
        const float* brow = B_s + k * 130 + tj * 8;
        ull bv0 = *(const ull*)(brow + 0);
        ull bv1 = *(const ull*)(brow + 2);
        ull bv2 = *(const ull*)(brow + 4);
        ull bv3 = *(const ull*)(brow + 6);
#pragma unroll
        for (int rr = 0; rr < 4; rr++) {
            float a = A_s[(ti * 4 + rr) * 128 + k];
            ull a2 = pack2(a, a);
            ffma2(acc[rr][0], a2, bv0);
            ffma2(acc[rr][1], a2, bv1);
            ffma2(acc[rr][2], a2, bv2);
            ffma2(acc[rr][3], a2, bv3);
        }
    }

    float bx[4], by[4];
#pragma unroll
    for (int u = 0; u < 4; u++) {
        int cc = n0 + tj * 8 + u * 2;
        bx[u] = b1[cc] + b2[cc];
        by[u] = b1[cc + 1] + b2[cc + 1];
    }
#pragma unroll
    for (int rr = 0; rr < 4; rr++) {
        int gr = row0 + ti * 4 + rr;
#pragma unroll
        for (int u = 0; u < 4; u++) {
            float2 v = unpack2(acc[rr][u]);
            int cc = n0 + tj * 8 + u * 2;
            float2 o = make_float2(v.x + bx[u], v.y + by[u]);
            *(float2*)(out + (size_t)gr * G4 + cc) = o;
        }
    }
}

// ============================================================================
// Kernel 2: LSTM recurrence. 256 threads = 2 gates/thread, 4 batch lanes/CTA.
// Whh fp16 in smem [gate][136-pad k]: LDS.128 = 8 weights, bank-clean.
// h in smem [k][4 lanes]: one LDS.128 broadcast = both f32x2 operands.
// ============================================================================
#define LSTM_SMEM (512 * 136 * 2 + 128 * 4 * 4 + 4 * 512 * 4)

__global__ __launch_bounds__(256, 1) void lstm_kernel(const float* __restrict__ Whh_f,
                                                      const float* __restrict__ Whh_b) {
    extern __shared__ char smraw[];
    __half* w_s  = (__half*)smraw;                         // [512][136]
    float*  h_s  = (float*)(smraw + 512 * 136 * 2);        // [128][4]
    float*  pre_s = h_s + 128 * 4;                         // [4][512]

    const int tid = threadIdx.x;     // 0..255
    const int g0  = tid;
    const int g1  = tid + 256;
    const int dir = blockIdx.y;
    const int b0  = blockIdx.x * 4;
    const float* Whh = dir ? Whh_b : Whh_f;
    const float* xp  = dir ? g_xproj_b : g_xproj_f;
    float* hout      = g_hcat + dir * 128;

    // Whh -> smem fp16, row layout [g][k] with 136-half pad
    for (int i = tid; i < 512 * 128; i += 256) {
        int k = i & 127;
        int g = i >> 7;
        w_s[g * 136 + k] = __float2half(Whh[i]);
    }
    if (tid < 128) *(float4*)&h_s[tid * 4] = make_float4(0.f, 0.f, 0.f, 0.f);
    float c[4] = {0.f, 0.f, 0.f, 0.f};
    __syncthreads();

    for (int s = 0; s < L_SEQ; ++s) {
        const int l = dir ? (L_SEQ - 1 - s) : s;
        const float* xrow = xp + ((size_t)l * B_N + b0) * G4;
        // x-projection loads (issued before gemv; consumed after -> latency hidden)
        float x00 = xrow[g0], x01 = xrow[512 + g0], x02 = xrow[1024 + g0], x03 = xrow[1536 + g0];
        float x10 = xrow[g1], x11 = xrow[512 + g1], x12 = xrow[1024 + g1], x13 = xrow[1536 + g1];

        ull A00 = 0ull, A01 = 0ull;   // gate g0: lanes (0,1), (2,3)
        ull A10 = 0ull, A11 = 0ull;   // gate g1
#pragma unroll 2
        for (int k = 0; k < 128; k += 8) {
            uint4 wv0 = *(const uint4*)(w_s + g0 * 136 + k);
            uint4 wv1 = *(const uint4*)(w_s + g1 * 136 + k);
            const unsigned* w0u = (const unsigned*)&wv0;
            const unsigned* w1u = (const unsigned*)&wv1;
#pragma unroll
            for (int u = 0; u < 4; ++u) {
                float2 fa = __half22float2(*(const __half2*)&w0u[u]);
                float2 fb = __half22float2(*(const __half2*)&w1u[u]);
                const int ka = k + 2 * u;
                ulonglong2 hva = *(const ulonglong2*)(h_s + ka * 4);       // k=ka
                ulonglong2 hvb = *(const ulonglong2*)(h_s + ka * 4 + 4);   // k=ka+1
                ull wa = pack2(fa.x, fa.x);
                ffma2(A00, wa, hva.x);
                ffma2(A01, wa, hva.y);
                ull wc = pack2(fb.x, fb.x);
                ffma2(A10, wc, hva.x);
                ffma2(A11, wc, hva.y);
                ull wb = pack2(fa.y, fa.y);
                ffma2(A00, wb, hvb.x);
                ffma2(A01, wb, hvb.y);
                ull wd = pack2(fb.y, fb.y);
                ffma2(A10, wd, hvb.x);
                ffma2(A11, wd, hvb.y);
            }
        }
        float2 a00 = unpack2(A00), a01 = unpack2(A01);
        float2 a10 = unpack2(A10), a11 = unpack2(A11);
        pre_s[0 * 512 + g0] = a00.x + x00;
        pre_s[1 * 512 + g0] = a00.y + x01;
        pre_s[2 * 512 + g0] = a01.x + x02;
        pre_s[3 * 512 + g0] = a01.y + x03;
        pre_s[0 * 512 + g1] = a10.x + x10;
        pre_s[1 * 512 + g1] = a10.y + x11;
        pre_s[2 * 512 + g1] = a11.x + x12;
        pre_s[3 * 512 + g1] = a11.y + x13;
        __syncthreads();

        if (tid < 128) {
            float hv[4];
#pragma unroll
            for (int bb = 0; bb < 4; ++bb) {
                float gi = pre_s[bb * 512 + tid];
                float gf = pre_s[bb * 512 + tid + 128];
                float gg = pre_s[bb * 512 + tid + 256];
                float go = pre_s[bb * 512 + tid + 384];
                float cn = sig_fast(gf) * c[bb] + sig_fast(gi) * tanh_fast(gg);
                c[bb] = cn;
                hv[bb] = sig_fast(go) * tanh_fast(cn);
            }
            *(float4*)&h_s[tid * 4] = make_float4(hv[0], hv[1], hv[2], hv[3]);
            size_t ho = ((size_t)l * B_N + b0) * 256 + tid;
            hout[ho]       = hv[0];
            hout[ho + 256] = hv[1];
            hout[ho + 512] = hv[2];
            hout[ho + 768] = hv[3];
        }
        __syncthreads();
    }
}

// ============================================================================
// Kernel 3: emis[l,b,t] = hcat[l,b,:] . Wout[t] + bout[t]
// ============================================================================
#define EMIS_SMEM ((48 * 257 + 16 * 256) * 4)

__global__ __launch_bounds__(256) void emis_kernel(const float* __restrict__ Wout,
                                                   const float* __restrict__ bout) {
    extern __shared__ float sm[];
    float* Wout_s = sm;                  // [48][257] padded
    float* hrow   = sm + 48 * 257;       // [16][256]

    const int tid = threadIdx.x;
    const int row0 = blockIdx.x * 16;    // row = l*B + b

    for (int i = tid; i < 48 * 256; i += 256) {
        int t = i >> 8;
        int k = i & 255;
        Wout_s[t * 257 + k] = Wout[i];
    }
    const float4* hsrc = (const float4*)(g_hcat + (size_t)row0 * 256);
    for (int i = tid; i < 16 * 64; i += 256) ((float4*)hrow)[i] = hsrc[i];
    __syncthreads();

    for (int o = tid; o < 16 * 48; o += 256) {
        int r = o / 48;
        int t = o % 48;
        const float* hp = hrow + r * 256;
        const float* wp = Wout_s + t * 257;
        float a0 = 0.f, a1 = 0.f, a2 = 0.f, a3 = 0.f;
#pragma unroll 4
        for (int k = 0; k < 256; k += 4) {
            a0 = fmaf(hp[k], wp[k], a0);
            a1 = fmaf(hp[k + 1], wp[k + 1], a1);
            a2 = fmaf(hp[k + 2], wp[k + 2], a2);
            a3 = fmaf(hp[k + 3], wp[k + 3], a3);
        }
        g_emis[(size_t)(row0 + r) * T_TAG + t] = bout[t] + (a0 + a1) + (a2 + a3);
    }
}

// ============================================================================
// Kernel 4: CRF numerator + forward algorithm per batch element.
// Double-buffered score (1 sync/step), candidate values held in regs,
// 4-way ILP on max and exp-sum chains.
// ============================================================================
__global__ __launch_bounds__(64) void crf_kernel(const int* __restrict__ words,
                                                 const int* __restrict__ tags,
                                                 const float* __restrict__ trans,
                                                 const float* __restrict__ start_trans,
                                                 const float* __restrict__ end_trans) {
    __shared__ float trans_s[48 * 48];
    __shared__ float sc[2][48];
    __shared__ float red[64];

    const int b = blockIdx.x;
    const int tid = threadIdx.x;

    for (int i = tid; i < 48 * 48; i += 64) trans_s[i] = trans[i];

    // sequence length (prefix mask == words != 0)
    int cnt = 0;
    for (int l = tid; l < L_SEQ; l += 64) cnt += (words[b * L_SEQ + l] != 0) ? 1 : 0;
    red[tid] = (float)cnt;
    __syncthreads();
    for (int sft = 32; sft > 0; sft >>= 1) {
        if (tid < sft) red[tid] += red[tid + sft];
        __syncthreads();
    }
    const int len = (int)red[0];
    __syncthreads();

    // numerator partials (l = 1 .. len-1)
    float np = 0.f;
    for (int l = 1 + tid; l < len; l += 64) {
        int tp = tags[b * L_SEQ + l - 1];
        int tc = tags[b * L_SEQ + l];
        np += trans_s[tp * 48 + tc] + g_emis[((size_t)l * B_N + b) * T_TAG + tc];
    }
    red[tid] = np;
    __syncthreads();
    for (int sft = 32; sft > 0; sft >>= 1) {
        if (tid < sft) red[tid] += red[tid + sft];
        __syncthreads();
    }
    // red[0] now holds interior numerator sum; untouched below.

    // denominator: forward algorithm
    if (tid < 48) sc[0][tid] = start_trans[tid] + g_emis[(size_t)b * T_TAG + tid];
    __syncthreads();
    int cur = 0;
    for (int l = 1; l < len; ++l) {
        if (tid < 48) {
            const int j = tid;
            float em = g_emis[((size_t)l * B_N + b) * T_TAG + j];
            float v[48];
            float m0 = -1e30f, m1 = -1e30f, m2 = -1e30f, m3 = -1e30f;
#pragma unroll
            for (int i = 0; i < 48; i += 4) {
                v[i]     = sc[cur][i]     + trans_s[i * 48 + j];
                v[i + 1] = sc[cur][i + 1] + trans_s[(i + 1) * 48 + j];
                v[i + 2] = sc[cur][i + 2] + trans_s[(i + 2) * 48 + j];
                v[i + 3] = sc[cur][i + 3] + trans_s[(i + 3) * 48 + j];
                m0 = fmaxf(m0, v[i]);
                m1 = fmaxf(m1, v[i + 1]);
                m2 = fmaxf(m2, v[i + 2]);
                m3 = fmaxf(m3, v[i + 3]);
            }
            float m = fmaxf(fmaxf(m0, m1), fmaxf(m2, m3));
            float s0 = 0.f, s1 = 0.f, s2 = 0.f, s3 = 0.f;
#pragma unroll
            for (int i = 0; i < 48; i += 4) {
                s0 += __expf(v[i] - m);
                s1 += __expf(v[i + 1] - m);
                s2 += __expf(v[i + 2] - m);
                s3 += __expf(v[i + 3] - m);
            }
            sc[cur ^ 1][j] = m + __logf((s0 + s1) + (s2 + s3)) + em;
        }
        __syncthreads();
        cur ^= 1;
    }

    if (tid == 0) {
        float mx = -1e30f;
        for (int j = 0; j < 48; ++j) mx = fmaxf(mx, sc[cur][j] + end_trans[j]);
        float ssum = 0.f;
        for (int j = 0; j < 48; ++j) ssum += __expf(sc[cur][j] + end_trans[j] - mx);
        float denom = mx + __logf(ssum);

        int t0 = tags[b * L_SEQ + 0];
        int tlast = tags[b * L_SEQ + (len - 1)];
        float num = red[0] + start_trans[t0] + g_emis[(size_t)b * T_TAG + t0] + end_trans[tlast];
        g_llh[b] = num - denom;
    }
}

// ============================================================================
// Kernel 5: final reduction -> out[0] = -mean(llh)
// ============================================================================
__global__ __launch_bounds__(256) void final_kernel(float* __restrict__ out) {
    __shared__ float red[256];
    int tid = threadIdx.x;
    red[tid] = g_llh[tid];
    __syncthreads();
    for (int s = 128; s > 0; s >>= 1) {
        if (tid < s) red[tid] += red[tid + s];
        __syncthreads();
    }
    if (tid == 0) out[0] = -red[0] / (float)B_N;
}

// ============================================================================
// launch
// ============================================================================
extern "C" void kernel_launch(void* const* d_in, const int* in_sizes, int n_in,
                              void* d_out, int out_size) {
    const int*   words  = (const int*)d_in[0];
    const int*   tags   = (const int*)d_in[1];
    // d_in[2] = mask (unused; derived from words != 0)
    const float* emb    = (const float*)d_in[3];
    const float* Wih_f  = (const float*)d_in[4];
    const float* Whh_f  = (const float*)d_in[5];
    const float* bih_f  = (const float*)d_in[6];
    const float* bhh_f  = (const float*)d_in[7];
    const float* Wih_b  = (const float*)d_in[8];
    const float* Whh_b  = (const float*)d_in[9];
    const float* bih_b  = (const float*)d_in[10];
    const float* bhh_b  = (const float*)d_in[11];
    const float* Wout   = (const float*)d_in[12];
    const float* bout   = (const float*)d_in[13];
    const float* trans  = (const float*)d_in[14];
    const float* st     = (const float*)d_in[15];
    const float* et     = (const float*)d_in[16];
    float* out = (float*)d_out;

    cudaFuncSetAttribute(xproj_kernel, cudaFuncAttributeMaxDynamicSharedMemorySize,
                         XPROJ_SMEM);
    cudaFuncSetAttribute(lstm_kernel, cudaFuncAttributeMaxDynamicSharedMemorySize,
                         LSTM_SMEM);
    cudaFuncSetAttribute(emis_kernel, cudaFuncAttributeMaxDynamicSharedMemorySize,
                         EMIS_SMEM);

    // 1) input projections for both directions (embedding gather fused)
    xproj_kernel<<<dim3(4, (L_SEQ * B_N) / 64, 2), 256, XPROJ_SMEM>>>(
        words, emb, Wih_f, bih_f, bhh_f, Wih_b, bih_b, bhh_b);

    // 2) recurrent BiLSTM: 64 CTAs x 2 directions, 4 batch lanes per CTA
    lstm_kernel<<<dim3(B_N / 4, 2), 256, LSTM_SMEM>>>(Whh_f, Whh_b);

    // 3) emissions
    emis_kernel<<<(L_SEQ * B_N) / 16, 256, EMIS_SMEM>>>(Wout, bout);

    // 4) CRF per batch element
    crf_kernel<<<B_N, 64>>>(words, tags, trans, st, et);

    // 5) reduce to scalar
    final_kernel<<<1, 256>>>(out);
}

// round 6
// speedup vs baseline: 1.3650x; 1.1059x over previous
#include <cuda_runtime.h>
#include <cuda_fp16.h>
#include <cuda_bf16.h>
#include <cstdint>

// ---------------- problem constants ----------------
#define L_SEQ 512
#define B_N   256
#define E_DIM 128
#define H_DIM 128
#define G4    512     // 4*H
#define T_TAG 48
#define NB    8       // batch lanes per LSTM CTA (mma N=8)

typedef unsigned long long ull;

// ---------------- scratch (device globals; no allocation allowed) ----------------
__device__ float g_xproj_f[(size_t)L_SEQ * B_N * G4];   // 256 MiB
__device__ float g_xproj_b[(size_t)L_SEQ * B_N * G4];   // 256 MiB
__device__ float g_hcat[(size_t)L_SEQ * B_N * 256];     // 128 MiB  [l][b][2H]
__device__ float g_emis[(size_t)L_SEQ * B_N * T_TAG];   // 24 MiB
__device__ float g_llh[B_N];

// ---------------- generic helpers ----------------
__device__ __forceinline__ ull pack2(float x, float y) {
    ull r;
    asm("mov.b64 %0, {%1, %2};" : "=l"(r) : "f"(x), "f"(y));
    return r;
}
__device__ __forceinline__ void ffma2(ull& d, ull a, ull b) {
    asm("fma.rn.f32x2 %0, %1, %2, %0;" : "+l"(d) : "l"(a), "l"(b));
}
__device__ __forceinline__ float2 unpack2(ull v) {
    float2 r;
    asm("mov.b64 {%0, %1}, %2;" : "=f"(r.x), "=f"(r.y) : "l"(v));
    return r;
}
__device__ __forceinline__ float tanh_fast(float x) {
    float y;
    asm("tanh.approx.f32 %0, %1;" : "=f"(y) : "f"(x));
    return y;
}
__device__ __forceinline__ float sig_fast(float x) {
    return fmaf(0.5f, tanh_fast(0.5f * x), 0.5f);
}
__device__ __forceinline__ uint32_t smem_u32(const void* p) {
    uint32_t a;
    asm("{ .reg .u64 t; cvta.to.shared.u64 t, %1; cvt.u32.u64 %0, t; }" : "=r"(a) : "l"(p));
    return a;
}
__device__ __forceinline__ uint32_t bf2(float x, float y) {
    __nv_bfloat162 t = __floats2bfloat162_rn(x, y);
    return *(uint32_t*)&t;
}
__device__ __forceinline__ void mma_bf16(float* d, const uint32_t* a, const uint32_t* b) {
    asm volatile(
        "mma.sync.aligned.m16n8k16.row.col.f32.bf16.bf16.f32 "
        "{%0,%1,%2,%3}, {%4,%5,%6,%7}, {%8,%9}, {%0,%1,%2,%3};"
        : "+f"(d[0]), "+f"(d[1]), "+f"(d[2]), "+f"(d[3])
        : "r"(a[0]), "r"(a[1]), "r"(a[2]), "r"(a[3]), "r"(b[0]), "r"(b[1]));
}
__device__ __forceinline__ void ldmatrix_x2_trans(uint32_t* r, uint32_t addr) {
    asm volatile("ldmatrix.sync.aligned.m8n8.x2.trans.shared.b16 {%0,%1}, [%2];"
                 : "=r"(r[0]), "=r"(r[1]) : "r"(addr));
}

// ============================================================================
// Kernel 1: xproj[l,b,g] = emb[words[b,l]] @ Wih^T + (bih + bhh)   (both dirs)
// ============================================================================
#define XPROJ_SMEM ((64 * 128 + 128 * 130) * 4)

__global__ __launch_bounds__(256, 2) void xproj_kernel(
    const int* __restrict__ words, const float* __restrict__ emb,
    const float* __restrict__ Wih_f, const float* __restrict__ bih_f,
    const float* __restrict__ bhh_f, const float* __restrict__ Wih_b,
    const float* __restrict__ bih_b, const float* __restrict__ bhh_b) {
    extern __shared__ float sm[];
    float* A_s = sm;                 // [64][128]
    float* B_s = sm + 64 * 128;      // [128][130]

    const int dir = blockIdx.z;
    const float* Wih = dir ? Wih_b : Wih_f;
    const float* b1  = dir ? bih_b : bih_f;
    const float* b2  = dir ? bhh_b : bhh_f;
    float* out       = dir ? g_xproj_b : g_xproj_f;

    const int row0 = blockIdx.y * 64;
    const int n0   = blockIdx.x * 128;
    const int tid  = threadIdx.x;

    for (int i = tid; i < 64 * 32; i += 256) {
        int r = i >> 5;
        int k4 = i & 31;
        int grow = row0 + r;
        int l = grow >> 8;
        int b = grow & 255;
        int w = words[b * L_SEQ + l];
        float4 v = *(const float4*)(emb + (size_t)w * E_DIM + k4 * 4);
        *(float4*)(&A_s[r * 128 + k4 * 4]) = v;
    }
    for (int i = tid; i < 128 * 128; i += 256) {
        int k = i & 127;
        int c = i >> 7;
        B_s[k * 130 + c] = Wih[(size_t)(n0 + c) * E_DIM + k];
    }
    __syncthreads();

    const int ti = tid >> 4;
    const int tj = tid & 15;
    ull acc[4][4];
#pragma unroll
    for (int r = 0; r < 4; r++)
#pragma unroll
        for (int u = 0; u < 4; u++) acc[r][u] = 0ull;

#pragma unroll 8
    for (int k = 0; k < 128; ++k) {
        const float* brow = B_s + k * 130 + tj * 8;
        ull bv0 = *(const ull*)(brow + 0);
        ull bv1 = *(const ull*)(brow + 2);
        ull bv2 = *(const ull*)(brow + 4);
        ull bv3 = *(const ull*)(brow + 6);
#pragma unroll
        for (int rr = 0; rr < 4; rr++) {
            float a = A_s[(ti * 4 + rr) * 128 + k];
            ull a2 = pack2(a, a);
            ffma2(acc[rr][0], a2, bv0);
            ffma2(acc[rr][1], a2, bv1);
            ffma2(acc[rr][2], a2, bv2);
            ffma2(acc[rr][3], a2, bv3);
        }
    }

    float bx[4], by[4];
#pragma unroll
    for (int u = 0; u < 4; u++) {
        int cc = n0 + tj * 8 + u * 2;
        bx[u] = b1[cc] + b2[cc];
        by[u] = b1[cc + 1] + b2[cc + 1];
    }
#pragma unroll
    for (int rr = 0; rr < 4; rr++) {
        int gr = row0 + ti * 4 + rr;
#pragma unroll
        for (int u = 0; u < 4; u++) {
            float2 v = unpack2(acc[rr][u]);
            int cc = n0 + tj * 8 + u * 2;
            float2 o = make_float2(v.x + bx[u], v.y + by[u]);
            *(float2*)(out + (size_t)gr * G4 + cc) = o;
        }
    }
}

// ============================================================================
// Kernel 2: HMMA LSTM (mma.sync m16n8k16 bf16). 256 threads, 8 batch/CTA.
// Warp w owns gate tiles {w, w+8, w+16, w+24} => gates 16w+128q, so each
// thread's D fragments hold all 4 gates (i,f,g,o) of its (h,b) pairs.
// Whh A-fragments persist in registers; h double-buffered in smem bf16.
// ============================================================================
__global__ __launch_bounds__(256) void lstm_mma_kernel(const float* __restrict__ Whh_f,
                                                       const float* __restrict__ Whh_b) {
    __shared__ __align__(1024) uint32_t hbuf[2][128 * 4];   // [buf][k-row][4 x bf16x2]

    const int tid  = threadIdx.x;
    const int lane = tid & 31;
    const int wid  = tid >> 5;        // 0..7
    const int gid  = lane >> 2;       // 0..7
    const int tig  = lane & 3;        // 0..3
    const int dir  = blockIdx.y;
    const int b0   = blockIdx.x * NB;
    const float* Whh = dir ? Whh_b : Whh_f;
    const float* xp  = dir ? g_xproj_b : g_xproj_f;
    float* hout      = g_hcat + dir * 128;

    // ---- load Whh A-fragments into registers (bf16) ----
    uint32_t afr[4][8][4];
#pragma unroll
    for (int q = 0; q < 4; ++q) {
        const int r0 = 16 * wid + 128 * q + gid;
#pragma unroll
        for (int ks = 0; ks < 8; ++ks) {
            const int cc = ks * 16 + 2 * tig;
            float2 v00 = *(const float2*)(Whh + (size_t)r0 * 128 + cc);
            float2 v10 = *(const float2*)(Whh + (size_t)(r0 + 8) * 128 + cc);
            float2 v01 = *(const float2*)(Whh + (size_t)r0 * 128 + cc + 8);
            float2 v11 = *(const float2*)(Whh + (size_t)(r0 + 8) * 128 + cc + 8);
            afr[q][ks][0] = bf2(v00.x, v00.y);
            afr[q][ks][1] = bf2(v10.x, v10.y);
            afr[q][ks][2] = bf2(v01.x, v01.y);
            afr[q][ks][3] = bf2(v11.x, v11.y);
        }
    }

    // zero both h buffers (h_{-1} = 0)
    for (int i = tid; i < 2 * 128 * 4; i += 256) ((uint32_t*)hbuf)[i] = 0;
    __syncthreads();

    float cst[4] = {0.f, 0.f, 0.f, 0.f};

    // prefetch xproj for step 0: xv[q][p], p = (rowsel<<1)|bsel
    int l = dir ? (L_SEQ - 1) : 0;
    float xv[4][4];
#pragma unroll
    for (int q = 0; q < 4; ++q)
#pragma unroll
        for (int p = 0; p < 4; ++p) {
            int g = 16 * wid + 128 * q + gid + (p >> 1) * 8;
            int b = b0 + 2 * tig + (p & 1);
            xv[q][p] = xp[((size_t)l * B_N + b) * G4 + g];
        }

    const uint32_t hb0 = smem_u32(hbuf);
    int buf = 0;

    for (int s = 0; s < L_SEQ; ++s) {
        // ---- B fragments: h[k][b] bf16, ldmatrix.x2.trans per 16-k step ----
        uint32_t rb[8][2];
        const uint32_t base = hb0 + (uint32_t)buf * 2048 + ((uint32_t)(lane & 15) << 4);
#pragma unroll
        for (int ks = 0; ks < 8; ++ks) ldmatrix_x2_trans(rb[ks], base + ks * 256);

        // ---- 32 HMMA: D[q] = Whh_q . h ----
        float d[4][4];
#pragma unroll
        for (int q = 0; q < 4; ++q)
#pragma unroll
            for (int c = 0; c < 4; ++c) d[q][c] = 0.f;
#pragma unroll
        for (int ks = 0; ks < 8; ++ks)
#pragma unroll
            for (int q = 0; q < 4; ++q) mma_bf16(d[q], afr[q][ks], rb[ks]);

        // ---- prefetch next step's xproj (latency hidden behind act/sync) ----
        const int ln = dir ? (l - 1) : (l + 1);
        float xn[4][4];
        if (s + 1 < L_SEQ) {
#pragma unroll
            for (int q = 0; q < 4; ++q)
#pragma unroll
                for (int p = 0; p < 4; ++p) {
                    int g = 16 * wid + 128 * q + gid + (p >> 1) * 8;
                    int b = b0 + 2 * tig + (p & 1);
                    xn[q][p] = xp[((size_t)ln * B_N + b) * G4 + g];
                }
        }

        // ---- activations: thread owns (row0,b),(row0,b+1),(row0+8,b),(row0+8,b+1) ----
        float hv[4];
#pragma unroll
        for (int p = 0; p < 4; ++p) {
            float gi = d[0][p] + xv[0][p];
            float gf = d[1][p] + xv[1][p];
            float gg = d[2][p] + xv[2][p];
            float go = d[3][p] + xv[3][p];
            float cn = sig_fast(gf) * cst[p] + sig_fast(gi) * tanh_fast(gg);
            cst[p] = cn;
            hv[p] = sig_fast(go) * tanh_fast(cn);
        }

        // ---- write h: smem (other buffer, bf16) + gmem hcat (fp32) ----
        const int r0 = 16 * wid + gid;
        hbuf[buf ^ 1][r0 * 4 + tig]       = bf2(hv[0], hv[1]);
        hbuf[buf ^ 1][(r0 + 8) * 4 + tig] = bf2(hv[2], hv[3]);

        const size_t orow = ((size_t)l * B_N + b0 + 2 * tig) * 256;
        hout[orow + r0]           = hv[0];
        hout[orow + 256 + r0]     = hv[1];
        hout[orow + r0 + 8]       = hv[2];
        hout[orow + 256 + r0 + 8] = hv[3];

        __syncthreads();
        buf ^= 1;
        l = ln;
#pragma unroll
        for (int q = 0; q < 4; ++q)
#pragma unroll
            for (int p = 0; p < 4; ++p) xv[q][p] = xn[q][p];
    }
}

// ============================================================================
// Kernel 3: emis[l,b,t] = hcat[l,b,:] . Wout[t] + bout[t]
// ============================================================================
#define EMIS_SMEM ((48 * 257 + 16 * 256) * 4)

__global__ __launch_bounds__(256) void emis_kernel(const float* __restrict__ Wout,
                                                   const float* __restrict__ bout) {
    extern __shared__ float sm[];
    float* Wout_s = sm;                  // [48][257]
    float* hrow   = sm + 48 * 257;       // [16][256]

    const int tid = threadIdx.x;
    const int row0 = blockIdx.x * 16;

    for (int i = tid; i < 48 * 256; i += 256) {
        int t = i >> 8;
        int k = i & 255;
        Wout_s[t * 257 + k] = Wout[i];
    }
    const float4* hsrc = (const float4*)(g_hcat + (size_t)row0 * 256);
    for (int i = tid; i < 16 * 64; i += 256) ((float4*)hrow)[i] = hsrc[i];
    __syncthreads();

    for (int o = tid; o < 16 * 48; o += 256) {
        int r = o / 48;
        int t = o % 48;
        const float* hp = hrow + r * 256;
        const float* wp = Wout_s + t * 257;
        float a0 = 0.f, a1 = 0.f, a2 = 0.f, a3 = 0.f;
#pragma unroll 4
        for (int k = 0; k < 256; k += 4) {
            a0 = fmaf(hp[k], wp[k], a0);
            a1 = fmaf(hp[k + 1], wp[k + 1], a1);
            a2 = fmaf(hp[k + 2], wp[k + 2], a2);
            a3 = fmaf(hp[k + 3], wp[k + 3], a3);
        }
        g_emis[(size_t)(row0 + r) * T_TAG + t] = bout[t] + (a0 + a1) + (a2 + a3);
    }
}

// ============================================================================
// Kernel 4: CRF — 8 sequences per CTA (384 threads), shared forward loop.
// ============================================================================
#define CRF_NB 8

__global__ __launch_bounds__(384) void crf_kernel(const int* __restrict__ words,
                                                  const int* __restrict__ tags,
                                                  const float* __restrict__ trans,
                                                  const float* __restrict__ start_trans,
                                                  const float* __restrict__ end_trans) {
    __shared__ float trans_s[48 * 48];
    __shared__ float sc[2][CRF_NB][48];
    __shared__ float red_s[CRF_NB][48];
    __shared__ int   len_s[CRF_NB];
    __shared__ float num_s[CRF_NB];
    __shared__ int   lmax_s;

    const int tid = threadIdx.x;
    const int bl = tid / 48;
    const int j = tid - bl * 48;
    const int b = blockIdx.x * CRF_NB + bl;

    for (int i = tid; i < 48 * 48; i += 384) trans_s[i] = trans[i];
    if (tid == 0) lmax_s = 0;

    // sequence length (prefix mask == words != 0)
    int cnt = 0;
    for (int l = j; l < L_SEQ; l += 48) cnt += (words[b * L_SEQ + l] != 0) ? 1 : 0;
    red_s[bl][j] = (float)cnt;
    __syncthreads();
    if (j == 0) {
        float sum = 0.f;
        for (int i = 0; i < 48; ++i) sum += red_s[bl][i];
        int len = (int)sum;
        len_s[bl] = len;
        atomicMax(&lmax_s, len);
    }
    __syncthreads();
    const int len = len_s[bl];
    const int lmax = lmax_s;

    // numerator partials (l = 1 .. len-1)
    float np = 0.f;
    for (int l = 1 + j; l < len; l += 48) {
        int tp = tags[b * L_SEQ + l - 1];
        int tc = tags[b * L_SEQ + l];
        np += trans_s[tp * 48 + tc] + g_emis[((size_t)l * B_N + b) * T_TAG + tc];
    }
    red_s[bl][j] = np;
    __syncthreads();
    if (j == 0) {
        float sum = 0.f;
        for (int i = 0; i < 48; ++i) sum += red_s[bl][i];
        num_s[bl] = sum;
    }

    // forward algorithm
    sc[0][bl][j] = start_trans[j] + g_emis[(size_t)b * T_TAG + j];
    __syncthreads();
    int cur = 0;
    for (int l = 1; l < lmax; ++l) {
        float nv;
        {
            float em = g_emis[((size_t)l * B_N + b) * T_TAG + j];
            float v[48];
            float m0 = -1e30f, m1 = -1e30f, m2 = -1e30f, m3 = -1e30f;
#pragma unroll
            for (int i = 0; i < 48; i += 4) {
                v[i]     = sc[cur][bl][i]     + trans_s[i * 48 + j];
                v[i + 1] = sc[cur][bl][i + 1] + trans_s[(i + 1) * 48 + j];
                v[i + 2] = sc[cur][bl][i + 2] + trans_s[(i + 2) * 48 + j];
                v[i + 3] = sc[cur][bl][i + 3] + trans_s[(i + 3) * 48 + j];
                m0 = fmaxf(m0, v[i]);
                m1 = fmaxf(m1, v[i + 1]);
                m2 = fmaxf(m2, v[i + 2]);
                m3 = fmaxf(m3, v[i + 3]);
            }
            float m = fmaxf(fmaxf(m0, m1), fmaxf(m2, m3));
            float s0 = 0.f, s1 = 0.f, s2 = 0.f, s3 = 0.f;
#pragma unroll
            for (int i = 0; i < 48; i += 4) {
                s0 += __expf(v[i] - m);
                s1 += __expf(v[i + 1] - m);
                s2 += __expf(v[i + 2] - m);
                s3 += __expf(v[i + 3] - m);
            }
            nv = m + __logf((s0 + s1) + (s2 + s3)) + em;
        }
        sc[cur ^ 1][bl][j] = (l < len) ? nv : sc[cur][bl][j];
        __syncthreads();
        cur ^= 1;
    }

    if (j == 0) {
        float mx = -1e30f;
        for (int t = 0; t < 48; ++t) mx = fmaxf(mx, sc[cur][bl][t] + end_trans[t]);
        float ssum = 0.f;
        for (int t = 0; t < 48; ++t) ssum += __expf(sc[cur][bl][t] + end_trans[t] - mx);
        float denom = mx + __logf(ssum);

        int t0 = tags[b * L_SEQ + 0];
        int tlast = tags[b * L_SEQ + (len - 1)];
        float num = num_s[bl] + start_trans[t0] + g_emis[(size_t)b * T_TAG + t0] +
                    end_trans[tlast];
        g_llh[b] = num - denom;
    }
}

// ============================================================================
// Kernel 5: final reduction -> out[0] = -mean(llh)
// ============================================================================
__global__ __launch_bounds__(256) void final_kernel(float* __restrict__ out) {
    __shared__ float red[256];
    int tid = threadIdx.x;
    red[tid] = g_llh[tid];
    __syncthreads();
    for (int s = 128; s > 0; s >>= 1) {
        if (tid < s) red[tid] += red[tid + s];
        __syncthreads();
    }
    if (tid == 0) out[0] = -red[0] / (float)B_N;
}

// ============================================================================
// launch
// ============================================================================
extern "C" void kernel_launch(void* const* d_in, const int* in_sizes, int n_in,
                              void* d_out, int out_size) {
    const int*   words  = (const int*)d_in[0];
    const int*   tags   = (const int*)d_in[1];
    // d_in[2] = mask (unused; derived from words != 0)
    const float* emb    = (const float*)d_in[3];
    const float* Wih_f  = (const float*)d_in[4];
    const float* Whh_f  = (const float*)d_in[5];
    const float* bih_f  = (const float*)d_in[6];
    const float* bhh_f  = (const float*)d_in[7];
    const float* Wih_b  = (const float*)d_in[8];
    const float* Whh_b  = (const float*)d_in[9];
    const float* bih_b  = (const float*)d_in[10];
    const float* bhh_b  = (const float*)d_in[11];
    const float* Wout   = (const float*)d_in[12];
    const float* bout   = (const float*)d_in[13];
    const float* trans  = (const float*)d_in[14];
    const float* st     = (const float*)d_in[15];
    const float* et     = (const float*)d_in[16];
    float* out = (float*)d_out;

    cudaFuncSetAttribute(xproj_kernel, cudaFuncAttributeMaxDynamicSharedMemorySize,
                         XPROJ_SMEM);
    cudaFuncSetAttribute(emis_kernel, cudaFuncAttributeMaxDynamicSharedMemorySize,
                         EMIS_SMEM);

    // 1) input projections for both directions (embedding gather fused)
    xproj_kernel<<<dim3(4, (L_SEQ * B_N) / 64, 2), 256, XPROJ_SMEM>>>(
        words, emb, Wih_f, bih_f, bhh_f, Wih_b, bih_b, bhh_b);

    // 2) HMMA BiLSTM: 32 CTAs x 2 directions, 8 batch lanes per CTA
    lstm_mma_kernel<<<dim3(B_N / NB, 2), 256>>>(Whh_f, Whh_b);

    // 3) emissions
    emis_kernel<<<(L_SEQ * B_N) / 16, 256, EMIS_SMEM>>>(Wout, bout);

    // 4) CRF: 8 sequences per CTA
    crf_kernel<<<B_N / CRF_NB, 384>>>(words, tags, trans, st, et);

    // 5) reduce to scalar
    final_kernel<<<1, 256>>>(out);
}

// round 7
// speedup vs baseline: 2.8690x; 2.1018x over previous
#include <cuda_runtime.h>
#include <cuda_fp16.h>
#include <cuda_bf16.h>
#include <cstdint>

// ---------------- problem constants ----------------
#define L_SEQ 512
#define B_N   256
#define E_DIM 128
#define H_DIM 128
#define G4    512     // 4*H
#define T_TAG 48
#define NB    8       // batch lanes per LSTM CTA (mma N=8)

typedef unsigned long long ull;

// ---------------- scratch (device globals; no allocation allowed) ----------------
__device__ float g_xproj_f[(size_t)L_SEQ * B_N * G4];   // 256 MiB
__device__ float g_xproj_b[(size_t)L_SEQ * B_N * G4];   // 256 MiB
__device__ float g_hcat[(size_t)L_SEQ * B_N * 256];     // 128 MiB  [l][b][2H]
__device__ float g_emis[(size_t)L_SEQ * B_N * T_TAG];   // 24 MiB
__device__ float g_llh[B_N];

// ---------------- generic helpers ----------------
__device__ __forceinline__ float tanh_fast(float x) {
    float y;
    asm("tanh.approx.f32 %0, %1;" : "=f"(y) : "f"(x));
    return y;
}
__device__ __forceinline__ float sig_fast(float x) {
    return fmaf(0.5f, tanh_fast(0.5f * x), 0.5f);
}
__device__ __forceinline__ uint32_t smem_u32(const void* p) {
    uint32_t a;
    asm("{ .reg .u64 t; cvta.to.shared.u64 t, %1; cvt.u32.u64 %0, t; }" : "=r"(a) : "l"(p));
    return a;
}
__device__ __forceinline__ uint32_t bf2(float x, float y) {
    __nv_bfloat162 t = __floats2bfloat162_rn(x, y);
    return *(uint32_t*)&t;
}
__device__ __forceinline__ void mma_bf16(float* d, const uint32_t* a, const uint32_t* b) {
    asm volatile(
        "mma.sync.aligned.m16n8k16.row.col.f32.bf16.bf16.f32 "
        "{%0,%1,%2,%3}, {%4,%5,%6,%7}, {%8,%9}, {%0,%1,%2,%3};"
        : "+f"(d[0]), "+f"(d[1]), "+f"(d[2]), "+f"(d[3])
        : "r"(a[0]), "r"(a[1]), "r"(a[2]), "r"(a[3]), "r"(b[0]), "r"(b[1]));
}
__device__ __forceinline__ void ldmatrix_x2_trans(uint32_t* r, uint32_t addr) {
    asm volatile("ldmatrix.sync.aligned.m8n8.x2.trans.shared.b16 {%0,%1}, [%2];"
                 : "=r"(r[0]), "=r"(r[1]) : "r"(addr));
}
__device__ __forceinline__ void ldsm_x4(uint32_t* r, uint32_t a) {
    asm volatile("ldmatrix.sync.aligned.m8n8.x4.shared.b16 {%0,%1,%2,%3}, [%4];"
                 : "=r"(r[0]), "=r"(r[1]), "=r"(r[2]), "=r"(r[3]) : "r"(a));
}
__device__ __forceinline__ void ldsm_x2(uint32_t* r, uint32_t a) {
    asm volatile("ldmatrix.sync.aligned.m8n8.x2.shared.b16 {%0,%1}, [%2];"
                 : "=r"(r[0]), "=r"(r[1]) : "r"(a));
}
__device__ __forceinline__ void cp16(uint32_t dst, const void* src) {
    asm volatile("cp.async.ca.shared.global [%0], [%1], 16;" :: "r"(dst), "l"(src));
}

// ============================================================================
// Kernel 1: xproj = emb[words] @ Wih^T + (bih+bhh) via HMMA bf16.
// CTA tile: 128 rows x 128 gates, K=128. B in native [n][k] layout (row.col).
// ============================================================================
#define XPM_A_OFF   0
#define XPM_B_OFF   (128 * 136 * 2)
#define XPM_BIAS_OFF (2 * 128 * 136 * 2)
#define XPM_SMEM    (XPM_BIAS_OFF + 128 * 4)

__global__ __launch_bounds__(256) void xproj_mma_kernel(
    const int* __restrict__ words, const float* __restrict__ emb,
    const float* __restrict__ Wih_f, const float* __restrict__ bih_f,
    const float* __restrict__ bhh_f, const float* __restrict__ Wih_b,
    const float* __restrict__ bih_b, const float* __restrict__ bhh_b) {
    extern __shared__ char xsm[];
    __nv_bfloat16* A_s = (__nv_bfloat16*)(xsm + XPM_A_OFF);   // [128][136]
    __nv_bfloat16* B_s = (__nv_bfloat16*)(xsm + XPM_B_OFF);   // [128][136]
    float* bias_s      = (float*)(xsm + XPM_BIAS_OFF);        // [128]

    const int dir = blockIdx.z;
    const float* Wih = dir ? Wih_b : Wih_f;
    const float* b1  = dir ? bih_b : bih_f;
    const float* b2  = dir ? bhh_b : bhh_f;
    float* out       = dir ? g_xproj_b : g_xproj_f;

    const int row0 = blockIdx.y * 128;
    const int n0   = blockIdx.x * 128;
    const int tid  = threadIdx.x;

    if (tid < 128) bias_s[tid] = b1[n0 + tid] + b2[n0 + tid];

    // A: gathered embedding rows -> bf16 [r][k], 136-elem row pad
    {
        const int r = tid >> 1, hf = tid & 1;
        const int grow = row0 + r;
        const int l = grow >> 8, b = grow & 255;
        const int w = words[b * L_SEQ + l];
        const float4* src = (const float4*)(emb + (size_t)w * E_DIM + hf * 64);
        __nv_bfloat16* dst = A_s + r * 136 + hf * 64;
#pragma unroll
        for (int i = 0; i < 8; ++i) {
            float4 v0 = src[2 * i], v1 = src[2 * i + 1];
            uint4 pk;
            pk.x = bf2(v0.x, v0.y);
            pk.y = bf2(v0.z, v0.w);
            pk.z = bf2(v1.x, v1.y);
            pk.w = bf2(v1.z, v1.w);
            *(uint4*)(dst + i * 8) = pk;
        }
    }
    // B: Wih rows (native [gate][k]) -> bf16 [n][k]
    {
        const int r = tid >> 1, hf = tid & 1;
        const float4* src = (const float4*)(Wih + (size_t)(n0 + r) * E_DIM + hf * 64);
        __nv_bfloat16* dst = B_s + r * 136 + hf * 64;
#pragma unroll
        for (int i = 0; i < 8; ++i) {
            float4 v0 = src[2 * i], v1 = src[2 * i + 1];
            uint4 pk;
            pk.x = bf2(v0.x, v0.y);
            pk.y = bf2(v0.z, v0.w);
            pk.z = bf2(v1.x, v1.y);
            pk.w = bf2(v1.z, v1.w);
            *(uint4*)(dst + i * 8) = pk;
        }
    }
    __syncthreads();

    const uint32_t As = smem_u32(A_s), Bs = smem_u32(B_s);
    const int lane = tid & 31, wid = tid >> 5;
    const int m_base = (wid >> 1) * 32;   // 4 m-warps
    const int n_base = (wid & 1) * 64;    // 2 n-warps

    float d[2][8][4];
#pragma unroll
    for (int mt = 0; mt < 2; ++mt)
#pragma unroll
        for (int nt = 0; nt < 8; ++nt)
#pragma unroll
            for (int c = 0; c < 4; ++c) d[mt][nt][c] = 0.f;

    const int aq = lane >> 3;
    const uint32_t a_row = (uint32_t)((aq & 1) * 8 + (lane & 7));
    const uint32_t a_col = (uint32_t)((aq >> 1) * 16);
    const uint32_t b_row = (uint32_t)(lane & 7);
    const uint32_t b_col = (uint32_t)(((lane >> 3) & 1) * 16);

#pragma unroll
    for (int ks = 0; ks < 8; ++ks) {
        uint32_t a0[4], a1[4];
        ldsm_x4(a0, As + (m_base + 0 + a_row) * 272 + ks * 32 + a_col);
        ldsm_x4(a1, As + (m_base + 16 + a_row) * 272 + ks * 32 + a_col);
#pragma unroll
        for (int nt = 0; nt < 8; ++nt) {
            uint32_t bb[2];
            ldsm_x2(bb, Bs + (n_base + nt * 8 + b_row) * 272 + ks * 32 + b_col);
            mma_bf16(d[0][nt], a0, bb);
            mma_bf16(d[1][nt], a1, bb);
        }
    }

    const int r = lane >> 2, c = (lane & 3) * 2;
#pragma unroll
    for (int mt = 0; mt < 2; ++mt) {
        const int gr = row0 + m_base + mt * 16 + r;
#pragma unroll
        for (int nt = 0; nt < 8; ++nt) {
            const int gc = n_base + nt * 8 + c;
            const float bx = bias_s[gc], by = bias_s[gc + 1];
            float2 o0 = make_float2(d[mt][nt][0] + bx, d[mt][nt][1] + by);
            float2 o1 = make_float2(d[mt][nt][2] + bx, d[mt][nt][3] + by);
            *(float2*)(out + (size_t)gr * G4 + n0 + gc) = o0;
            *(float2*)(out + (size_t)(gr + 8) * G4 + n0 + gc) = o1;
        }
    }
}

// ============================================================================
// Kernel 2: HMMA LSTM. 256 threads, 8 batch/CTA, Whh A-frags in registers.
// xproj staged via cp.async 3-buffer pipeline (no persistent x registers).
// ============================================================================
#define LSTM_HBUF   0                     // 2 x 128 x 16B = 4096
#define LSTM_XBUF   4096                  // 3 x 8 x 516 floats = 49536
#define LSTM_SMEM   (4096 + 3 * 8 * 516 * 4)
#define XB_STRIDE   516                   // floats per batch row (bank-clean)
#define XB_BUFSZ    (8 * XB_STRIDE)       // floats per buffer

__global__ __launch_bounds__(256) void lstm_mma_kernel(const float* __restrict__ Whh_f,
                                                       const float* __restrict__ Whh_b) {
    extern __shared__ char smraw[];
    uint32_t* hbuf = (uint32_t*)(smraw + LSTM_HBUF);   // [2][128][4 bf16x2]
    float* xbuf    = (float*)(smraw + LSTM_XBUF);      // [3][8][516]

    const int tid  = threadIdx.x;
    const int lane = tid & 31;
    const int wid  = tid >> 5;        // 0..7
    const int gid  = lane >> 2;       // 0..7
    const int tig  = lane & 3;        // 0..3
    const int dir  = blockIdx.y;
    const int b0   = blockIdx.x * NB;
    const float* Whh = dir ? Whh_b : Whh_f;
    const float* xp  = dir ? g_xproj_b : g_xproj_f;
    float* hout      = g_hcat + dir * 128;

    const uint32_t hb_u32 = smem_u32(hbuf);
    const uint32_t xb_u32 = smem_u32(xbuf);

    // ---- Whh A-fragments in registers (bf16), 128 regs/thread ----
    uint32_t afr[4][8][4];
#pragma unroll
    for (int q = 0; q < 4; ++q) {
        const int r0 = 16 * wid + 128 * q + gid;
#pragma unroll
        for (int ks = 0; ks < 8; ++ks) {
            const int cc = ks * 16 + 2 * tig;
            float2 v00 = *(const float2*)(Whh + (size_t)r0 * 128 + cc);
            float2 v10 = *(const float2*)(Whh + (size_t)(r0 + 8) * 128 + cc);
            float2 v01 = *(const float2*)(Whh + (size_t)r0 * 128 + cc + 8);
            float2 v11 = *(const float2*)(Whh + (size_t)(r0 + 8) * 128 + cc + 8);
            afr[q][ks][0] = bf2(v00.x, v00.y);
            afr[q][ks][1] = bf2(v10.x, v10.y);
            afr[q][ks][2] = bf2(v01.x, v01.y);
            afr[q][ks][3] = bf2(v11.x, v11.y);
        }
    }

    // zero both h buffers
    for (int i = tid; i < 2 * 128 * 4; i += 256) hbuf[i] = 0;

    // prologue: prefetch x(0), x(1)
#pragma unroll
    for (int ps = 0; ps < 2; ++ps) {
        const int l = dir ? (L_SEQ - 1 - ps) : ps;
        const float* src = xp + ((size_t)l * B_N + b0) * G4;
#pragma unroll
        for (int rr = 0; rr < 4; ++rr) {
            int idx = tid + rr * 256;
            int brow = idx >> 7, c16 = idx & 127;
            cp16(xb_u32 + (uint32_t)(ps * XB_BUFSZ * 4 + brow * XB_STRIDE * 4 + c16 * 16),
                 src + brow * 512 + c16 * 4);
        }
        asm volatile("cp.async.commit_group;");
    }
    asm volatile("cp.async.wait_group 1;");   // x(0) ready
    __syncthreads();

    float cst[4] = {0.f, 0.f, 0.f, 0.f};

    for (int s = 0; s < L_SEQ; ++s) {
        const int l = dir ? (L_SEQ - 1 - s) : s;

        // ---- issue prefetch x(s+2) ----
        if (s + 2 < L_SEQ) {
            const int lf = dir ? (L_SEQ - 3 - s) : (s + 2);
            const float* src = xp + ((size_t)lf * B_N + b0) * G4;
            const uint32_t dbase = xb_u32 + (uint32_t)(((s + 2) % 3) * XB_BUFSZ * 4);
#pragma unroll
            for (int rr = 0; rr < 4; ++rr) {
                int idx = tid + rr * 256;
                int brow = idx >> 7, c16 = idx & 127;
                cp16(dbase + (uint32_t)(brow * XB_STRIDE * 4 + c16 * 16),
                     src + brow * 512 + c16 * 4);
            }
            asm volatile("cp.async.commit_group;");
        }

        // ---- B fragments from hbuf[s&1] ----
        uint32_t rb[8][2];
        const uint32_t base = hb_u32 + (uint32_t)((s & 1) * 2048) + ((uint32_t)(lane & 15) << 4);
#pragma unroll
        for (int ks = 0; ks < 8; ++ks) ldmatrix_x2_trans(rb[ks], base + ks * 256);

        // ---- 32 HMMA ----
        float d[4][4];
#pragma unroll
        for (int q = 0; q < 4; ++q)
#pragma unroll
            for (int c = 0; c < 4; ++c) d[q][c] = 0.f;
#pragma unroll
        for (int ks = 0; ks < 8; ++ks)
#pragma unroll
            for (int q = 0; q < 4; ++q) mma_bf16(d[q], afr[q][ks], rb[ks]);

        // ---- activations: x from smem buffer (s%3) ----
        const float* xbf = xbuf + (s % 3) * XB_BUFSZ + (2 * tig) * XB_STRIDE + 16 * wid + gid;
        float hv[4];
#pragma unroll
        for (int p = 0; p < 4; ++p) {
            const int xo = (p & 1) * XB_STRIDE + 8 * (p >> 1);
            float gi = d[0][p] + xbf[xo];
            float gf = d[1][p] + xbf[xo + 128];
            float gg = d[2][p] + xbf[xo + 256];
            float go = d[3][p] + xbf[xo + 384];
            float cn = sig_fast(gf) * cst[p] + sig_fast(gi) * tanh_fast(gg);
            cst[p] = cn;
            hv[p] = sig_fast(go) * tanh_fast(cn);
        }

        // ---- write h: smem (next buffer, bf16) + gmem hcat (fp32) ----
        const int r0 = 16 * wid + gid;
        hbuf[((s + 1) & 1) * 512 + r0 * 4 + tig]       = bf2(hv[0], hv[1]);
        hbuf[((s + 1) & 1) * 512 + (r0 + 8) * 4 + tig] = bf2(hv[2], hv[3]);

        const size_t orow = ((size_t)l * B_N + b0 + 2 * tig) * 256;
        hout[orow + r0]           = hv[0];
        hout[orow + 256 + r0]     = hv[1];
        hout[orow + r0 + 8]       = hv[2];
        hout[orow + 256 + r0 + 8] = hv[3];

        // ---- ensure x(s+1) complete, then publish h + x to all threads ----
        if (s + 2 < L_SEQ) {
            asm volatile("cp.async.wait_group 1;");
        } else {
            asm volatile("cp.async.wait_group 0;");
        }
        __syncthreads();
    }
}

// ============================================================================
// Kernel 3: emis[l,b,t] = hcat[l,b,:] . Wout[t] + bout[t]
// ============================================================================
#define EMIS_SMEM ((48 * 257 + 16 * 256) * 4)

__global__ __launch_bounds__(256) void emis_kernel(const float* __restrict__ Wout,
                                                   const float* __restrict__ bout) {
    extern __shared__ float sm[];
    float* Wout_s = sm;                  // [48][257]
    float* hrow   = sm + 48 * 257;       // [16][256]

    const int tid = threadIdx.x;
    const int row0 = blockIdx.x * 16;

    for (int i = tid; i < 48 * 256; i += 256) {
        int t = i >> 8;
        int k = i & 255;
        Wout_s[t * 257 + k] = Wout[i];
    }
    const float4* hsrc = (const float4*)(g_hcat + (size_t)row0 * 256);
    for (int i = tid; i < 16 * 64; i += 256) ((float4*)hrow)[i] = hsrc[i];
    __syncthreads();

    for (int o = tid; o < 16 * 48; o += 256) {
        int r = o / 48;
        int t = o % 48;
        const float* hp = hrow + r * 256;
        const float* wp = Wout_s + t * 257;
        float a0 = 0.f, a1 = 0.f, a2 = 0.f, a3 = 0.f;
#pragma unroll 4
        for (int k = 0; k < 256; k += 4) {
            a0 = fmaf(hp[k], wp[k], a0);
            a1 = fmaf(hp[k + 1], wp[k + 1], a1);
            a2 = fmaf(hp[k + 2], wp[k + 2], a2);
            a3 = fmaf(hp[k + 3], wp[k + 3], a3);
        }
        g_emis[(size_t)(row0 + r) * T_TAG + t] = bout[t] + (a0 + a1) + (a2 + a3);
    }
}

// ============================================================================
// Kernel 4: CRF — one WARP per sequence (8 warps/CTA). Forward recurrence via
// exp(trans) matvec: lse_i(s_i+T_ij) = m + log(sum_i e^{s_i-m} E_ij).
// ============================================================================
__global__ __launch_bounds__(256) void crf_kernel(const int* __restrict__ words,
                                                  const int* __restrict__ tags,
                                                  const float* __restrict__ trans,
                                                  const float* __restrict__ start_trans,
                                                  const float* __restrict__ end_trans) {
    __shared__ __align__(16) float E_s[48 * 48];    // exp(trans)
    __shared__ __align__(16) float tr_s[48 * 48];   // raw trans (numerator)
    __shared__ __align__(16) float p_s[8][48];

    const int tid = threadIdx.x;
    const int w = tid >> 5, lane = tid & 31;
    const int b = blockIdx.x * 8 + w;

    for (int i = tid; i < 48 * 48; i += 256) {
        float v = trans[i];
        tr_s[i] = v;
        E_s[i] = __expf(v);
    }
    __syncthreads();

    // sequence length (prefix mask == words != 0)
    int cnt = 0;
    for (int l = lane; l < L_SEQ; l += 32) cnt += (words[b * L_SEQ + l] != 0) ? 1 : 0;
#pragma unroll
    for (int o = 16; o; o >>= 1) cnt += __shfl_xor_sync(0xFFFFFFFFu, cnt, o);
    const int len = cnt;

    // numerator partials (l = 1 .. len-1)
    float np = 0.f;
    for (int l = 1 + lane; l < len; l += 32) {
        int tp = tags[b * L_SEQ + l - 1];
        int tc = tags[b * L_SEQ + l];
        np += tr_s[tp * 48 + tc] + g_emis[((size_t)l * B_N + b) * T_TAG + tc];
    }
#pragma unroll
    for (int o = 16; o; o >>= 1) np += __shfl_xor_sync(0xFFFFFFFFu, np, o);

    // forward algorithm: lane owns j1 = lane; lanes < 16 also own j2 = 32+lane
    const int j1 = lane;
    const int j2 = 32 + lane;
    const bool has2 = lane < 16;

    float s1 = start_trans[j1] + g_emis[(size_t)b * T_TAG + j1];
    float s2 = has2 ? (start_trans[j2] + g_emis[(size_t)b * T_TAG + j2]) : -1e30f;

    float em1 = 0.f, em2 = 0.f;
    if (len > 1) {
        const size_t eb = ((size_t)1 * B_N + b) * T_TAG;
        em1 = g_emis[eb + j1];
        em2 = has2 ? g_emis[eb + j2] : 0.f;
    }

    for (int l = 1; l < len; ++l) {
        // warp max
        float m = fmaxf(s1, s2);
#pragma unroll
        for (int o = 16; o; o >>= 1) m = fmaxf(m, __shfl_xor_sync(0xFFFFFFFFu, m, o));

        p_s[w][j1] = __expf(s1 - m);
        if (has2) p_s[w][j2] = __expf(s2 - m);
        __syncwarp();

        // prefetch next step's emissions
        float en1 = 0.f, en2 = 0.f;
        if (l + 1 < len) {
            const size_t eb = ((size_t)(l + 1) * B_N + b) * T_TAG;
            en1 = g_emis[eb + j1];
            en2 = has2 ? g_emis[eb + j2] : 0.f;
        }

        // matvec: acc_j = sum_i p_i * E[i][j]
        float a10 = 0.f, a11 = 0.f, a12 = 0.f, a13 = 0.f;
        float a20 = 0.f, a21 = 0.f, a22 = 0.f, a23 = 0.f;
        const float4* p4 = (const float4*)p_s[w];
#pragma unroll
        for (int i4 = 0; i4 < 12; ++i4) {
            float4 pv = p4[i4];
            const int i = i4 * 4;
            a10 = fmaf(pv.x, E_s[i * 48 + j1], a10);
            a11 = fmaf(pv.y, E_s[(i + 1) * 48 + j1], a11);
            a12 = fmaf(pv.z, E_s[(i + 2) * 48 + j1], a12);
            a13 = fmaf(pv.w, E_s[(i + 3) * 48 + j1], a13);
            if (has2) {
                a20 = fmaf(pv.x, E_s[i * 48 + j2], a20);
                a21 = fmaf(pv.y, E_s[(i + 1) * 48 + j2], a21);
                a22 = fmaf(pv.z, E_s[(i + 2) * 48 + j2], a22);
                a23 = fmaf(pv.w, E_s[(i + 3) * 48 + j2], a23);
            }
        }
        s1 = m + __logf((a10 + a11) + (a12 + a13)) + em1;
        if (has2) s2 = m + __logf((a20 + a21) + (a22 + a23)) + em2;
        em1 = en1;
        em2 = en2;
        __syncwarp();   // WAR: p_s reused next iteration
    }

    // termination
    float v1 = s1 + end_trans[j1];
    float v2 = has2 ? (s2 + end_trans[j2]) : -1e30f;
    float m = fmaxf(v1, v2);
#pragma unroll
    for (int o = 16; o; o >>= 1) m = fmaxf(m, __shfl_xor_sync(0xFFFFFFFFu, m, o));
    float sm = __expf(v1 - m) + (has2 ? __expf(v2 - m) : 0.f);
#pragma unroll
    for (int o = 16; o; o >>= 1) sm += __shfl_xor_sync(0xFFFFFFFFu, sm, o);

    if (lane == 0) {
        float denom = m + __logf(sm);
        int t0 = tags[b * L_SEQ + 0];
        int tlast = tags[b * L_SEQ + (len - 1)];
        float num = np + start_trans[t0] + g_emis[(size_t)b * T_TAG + t0] + end_trans[tlast];
        g_llh[b] = num - denom;
    }
}

// ============================================================================
// Kernel 5: final reduction -> out[0] = -mean(llh)
// ============================================================================
__global__ __launch_bounds__(256) void final_kernel(float* __restrict__ out) {
    __shared__ float red[256];
    int tid = threadIdx.x;
    red[tid] = g_llh[tid];
    __syncthreads();
    for (int s = 128; s > 0; s >>= 1) {
        if (tid < s) red[tid] += red[tid + s];
        __syncthreads();
    }
    if (tid == 0) out[0] = -red[0] / (float)B_N;
}

// ============================================================================
// launch
// ============================================================================
extern "C" void kernel_launch(void* const* d_in, const int* in_sizes, int n_in,
                              void* d_out, int out_size) {
    const int*   words  = (const int*)d_in[0];
    const int*   tags   = (const int*)d_in[1];
    // d_in[2] = mask (unused; derived from words != 0)
    const float* emb    = (const float*)d_in[3];
    const float* Wih_f  = (const float*)d_in[4];
    const float* Whh_f  = (const float*)d_in[5];
    const float* bih_f  = (const float*)d_in[6];
    const float* bhh_f  = (const float*)d_in[7];
    const float* Wih_b  = (const float*)d_in[8];
    const float* Whh_b  = (const float*)d_in[9];
    const float* bih_b  = (const float*)d_in[10];
    const float* bhh_b  = (const float*)d_in[11];
    const float* Wout   = (const float*)d_in[12];
    const float* bout   = (const float*)d_in[13];
    const float* trans  = (const float*)d_in[14];
    const float* st     = (const float*)d_in[15];
    const float* et     = (const float*)d_in[16];
    float* out = (float*)d_out;

    cudaFuncSetAttribute(xproj_mma_kernel, cudaFuncAttributeMaxDynamicSharedMemorySize,
                         XPM_SMEM);
    cudaFuncSetAttribute(lstm_mma_kernel, cudaFuncAttributeMaxDynamicSharedMemorySize,
                         LSTM_SMEM);
    cudaFuncSetAttribute(emis_kernel, cudaFuncAttributeMaxDynamicSharedMemorySize,
                         EMIS_SMEM);

    // 1) input projections via HMMA (128x128 tiles)
    xproj_mma_kernel<<<dim3(4, (L_SEQ * B_N) / 128, 2), 256, XPM_SMEM>>>(
        words, emb, Wih_f, bih_f, bhh_f, Wih_b, bih_b, bhh_b);

    // 2) HMMA BiLSTM with cp.async x staging: 32 CTAs x 2 dirs
    lstm_mma_kernel<<<dim3(B_N / NB, 2), 256, LSTM_SMEM>>>(Whh_f, Whh_b);

    // 3) emissions
    emis_kernel<<<(L_SEQ * B_N) / 16, 256, EMIS_SMEM>>>(Wout, bout);

    // 4) CRF: one warp per sequence
    crf_kernel<<<B_N / 8, 256>>>(words, tags, trans, st, et);

    // 5) reduce to scalar
    final_kernel<<<1, 256>>>(out);
}